// round 1
// baseline (speedup 1.0000x reference)
#include <cuda_runtime.h>
#include <math.h>

#define B_ 2
#define S_ 2048
#define E_ 1024
#define H_ 16
#define D_ 64
#define M_ (B_*S_)   // 4096 rows for the projection GEMMs

// Scratch (allocation-free rule: __device__ globals)
__device__ float g_q[B_*H_*S_*D_];    // [B,H,S,D]
__device__ float g_k[B_*H_*S_*D_];
__device__ float g_v[B_*H_*S_*D_];
__device__ float g_ctx[B_*S_*E_];     // [B,S,E]

// ---------------------------------------------------------------------------
// GEMM: C[m][n] = sum_k X[m][k] * W[n][k] + bias[n]
//   (both X and W are K-contiguous row-major; this matches einsum("bse,fe->bsf"))
// MODE 0: write out row-major [M_][E_]   (final projection)
// MODE 1: write out as [B,H,S,D]         (QKV projections, n = h*64 + d)
// Tiling: 128x128x8, 256 threads, 8x8 per-thread microtile, reg prefetch.
// ---------------------------------------------------------------------------
template<int MODE>
__global__ void __launch_bounds__(256, 2) gemm_xwT(
    const float* __restrict__ X, const float* __restrict__ W,
    const float* __restrict__ bias, float* __restrict__ out)
{
    __shared__ float Ast[8][132];   // [k][m], pad 132 (16B-aligned rows, conflict-free)
    __shared__ float Bst[8][132];   // [k][n]

    const int K = E_;
    const int tid = threadIdx.x;
    const int tx = tid & 15, ty = tid >> 4;
    const int m0 = blockIdx.y * 128;
    const int n0 = blockIdx.x * 128;
    const int lr = tid >> 1;          // 0..127
    const int lc = (tid & 1) * 4;     // 0 or 4

    float acc[8][8];
    #pragma unroll
    for (int i = 0; i < 8; i++)
        #pragma unroll
        for (int j = 0; j < 8; j++) acc[i][j] = 0.f;

    const float* Ap = X + (size_t)(m0 + lr) * K + lc;
    const float* Bp = W + (size_t)(n0 + lr) * K + lc;

    float4 a = *(const float4*)(Ap);
    float4 b = *(const float4*)(Bp);

    for (int k0 = 0; k0 < K; k0 += 8) {
        Ast[lc+0][lr] = a.x; Ast[lc+1][lr] = a.y; Ast[lc+2][lr] = a.z; Ast[lc+3][lr] = a.w;
        Bst[lc+0][lr] = b.x; Bst[lc+1][lr] = b.y; Bst[lc+2][lr] = b.z; Bst[lc+3][lr] = b.w;
        __syncthreads();

        if (k0 + 8 < K) {   // prefetch next tile into registers (hide DRAM/L2 latency)
            a = *(const float4*)(Ap + k0 + 8);
            b = *(const float4*)(Bp + k0 + 8);
        }

        #pragma unroll
        for (int k = 0; k < 8; k++) {
            float4 a0 = *(const float4*)&Ast[k][ty*8];
            float4 a1 = *(const float4*)&Ast[k][ty*8+4];
            float4 b0 = *(const float4*)&Bst[k][tx*8];
            float4 b1 = *(const float4*)&Bst[k][tx*8+4];
            float ar[8] = {a0.x,a0.y,a0.z,a0.w,a1.x,a1.y,a1.z,a1.w};
            float br[8] = {b0.x,b0.y,b0.z,b0.w,b1.x,b1.y,b1.z,b1.w};
            #pragma unroll
            for (int i = 0; i < 8; i++)
                #pragma unroll
                for (int j = 0; j < 8; j++)
                    acc[i][j] = fmaf(ar[i], br[j], acc[i][j]);
        }
        __syncthreads();
    }

    #pragma unroll
    for (int i = 0; i < 8; i++) {
        int m = m0 + ty*8 + i;
        #pragma unroll
        for (int j = 0; j < 8; j++) {
            int n = n0 + tx*8 + j;
            float v = acc[i][j] + bias[n];
            if (MODE == 0) {
                out[(size_t)m * E_ + n] = v;
            } else {
                int bb = m >> 11;          // m / S_
                int s  = m & (S_ - 1);
                int h  = n >> 6;           // n / D_
                int d  = n & 63;
                out[((size_t)(bb * H_ + h) * S_ + s) * D_ + d] = v;
            }
        }
    }
}

// ---------------------------------------------------------------------------
// Flash attention, fp32. One block handles 64 query rows for one (b,h).
// BR=BC=64, D=64. 256 threads, each owns a 4x4 tile (scores) and 4 rows x 4 d
// (output accumulator). Online softmax with per-thread replicated row stats.
// ctx written in [B,S,E] layout for the output projection.
// ---------------------------------------------------------------------------
__global__ void __launch_bounds__(256) flash_attn(const float* __restrict__ mask)
{
    extern __shared__ float sm[];
    float* Qst  = sm;                 // [64][68] : Qst[d][r]  (transposed)
    float* Kst  = Qst + 64*68;        // [64][68] : Kst[d][c]  (transposed)
    float* Vs   = Kst + 64*68;        // [64][68] : Vs[c][d]
    float* Ps   = Vs  + 64*68;        // [64][68] : Ps[r][c]
    float* redA = Ps  + 64*68;        // [64][16] row-max partials
    float* redB = redA + 64*16;       // [64][16] row-sum partials

    const int tid = threadIdx.x;
    const int tx = tid & 15, ty = tid >> 4;
    const int bh = blockIdx.y;                  // b*H + h
    const int row0 = blockIdx.x * 64;

    const float* qb = g_q + ((size_t)bh * S_ + row0) * D_;
    const float* kb = g_k + (size_t)bh * S_ * D_;
    const float* vb = g_v + (size_t)bh * S_ * D_;

    // Load Q tile transposed: Qst[d][r] = q[row0+r][d]
    #pragma unroll
    for (int i = 0; i < 4; i++) {
        int e = tid + i * 256;             // 0..1023 float4 slots
        int r = e >> 4, dq = (e & 15) * 4;
        float4 v = *(const float4*)(qb + (size_t)r * D_ + dq);
        Qst[(dq+0)*68 + r] = v.x;
        Qst[(dq+1)*68 + r] = v.y;
        Qst[(dq+2)*68 + r] = v.z;
        Qst[(dq+3)*68 + r] = v.w;
    }

    float O[4][4];
    float mrow[4], lrow[4];
    #pragma unroll
    for (int i = 0; i < 4; i++) {
        mrow[i] = -1e30f; lrow[i] = 0.f;
        #pragma unroll
        for (int j = 0; j < 4; j++) O[i][j] = 0.f;
    }

    const float scale = 0.125f;   // 1/sqrt(64)

    for (int t = 0; t < S_ / 64; t++) {
        const int col0 = t * 64;

        // Load K tile transposed + V tile natural
        #pragma unroll
        for (int i = 0; i < 4; i++) {
            int e = tid + i * 256;
            int c = e >> 4, dq = (e & 15) * 4;
            float4 kv = *(const float4*)(kb + (size_t)(col0 + c) * D_ + dq);
            Kst[(dq+0)*68 + c] = kv.x;
            Kst[(dq+1)*68 + c] = kv.y;
            Kst[(dq+2)*68 + c] = kv.z;
            Kst[(dq+3)*68 + c] = kv.w;
            float4 vv = *(const float4*)(vb + (size_t)(col0 + c) * D_ + dq);
            *(float4*)&Vs[c*68 + dq] = vv;
        }
        __syncthreads();

        // Scores: s[i][j] = sum_d Q[r][d]*K[c][d]
        float s[4][4];
        #pragma unroll
        for (int i = 0; i < 4; i++)
            #pragma unroll
            for (int j = 0; j < 4; j++) s[i][j] = 0.f;

        #pragma unroll 8
        for (int k = 0; k < 64; k++) {
            float4 aq = *(const float4*)&Qst[k*68 + ty*4];
            float4 bq = *(const float4*)&Kst[k*68 + tx*4];
            float ar[4] = {aq.x, aq.y, aq.z, aq.w};
            float br[4] = {bq.x, bq.y, bq.z, bq.w};
            #pragma unroll
            for (int i = 0; i < 4; i++)
                #pragma unroll
                for (int j = 0; j < 4; j++)
                    s[i][j] = fmaf(ar[i], br[j], s[i][j]);
        }

        // scale + additive mask
        #pragma unroll
        for (int i = 0; i < 4; i++) {
            int rg = row0 + ty*4 + i;
            float4 mk = *(const float4*)(mask + (size_t)rg * S_ + col0 + tx*4);
            s[i][0] = s[i][0]*scale + mk.x;
            s[i][1] = s[i][1]*scale + mk.y;
            s[i][2] = s[i][2]*scale + mk.z;
            s[i][3] = s[i][3]*scale + mk.w;
        }

        // Row-max reduce across the 16 tx threads
        #pragma unroll
        for (int i = 0; i < 4; i++) {
            float pm = fmaxf(fmaxf(s[i][0], s[i][1]), fmaxf(s[i][2], s[i][3]));
            redA[(ty*4 + i) * 16 + tx] = pm;
        }
        __syncthreads();

        float mnew[4], alpha[4];
        #pragma unroll
        for (int i = 0; i < 4; i++) {
            int r = ty*4 + i;
            float mx = redA[r*16];
            #pragma unroll
            for (int q = 1; q < 16; q++) mx = fmaxf(mx, redA[r*16 + q]);
            mnew[i]  = fmaxf(mrow[i], mx);
            alpha[i] = __expf(mrow[i] - mnew[i]);
        }

        // P = exp(s - mnew); write Ps and partial row sums
        #pragma unroll
        for (int i = 0; i < 4; i++) {
            float sum = 0.f;
            #pragma unroll
            for (int j = 0; j < 4; j++) {
                float p = __expf(s[i][j] - mnew[i]);
                Ps[(ty*4 + i) * 68 + tx*4 + j] = p;
                sum += p;
            }
            redB[(ty*4 + i) * 16 + tx] = sum;
        }
        __syncthreads();

        #pragma unroll
        for (int i = 0; i < 4; i++) {
            int r = ty*4 + i;
            float sum = 0.f;
            #pragma unroll
            for (int q = 0; q < 16; q++) sum += redB[r*16 + q];
            lrow[i] = lrow[i] * alpha[i] + sum;
            mrow[i] = mnew[i];
            #pragma unroll
            for (int j = 0; j < 4; j++) O[i][j] *= alpha[i];
        }

        // O += P @ V
        #pragma unroll 8
        for (int c = 0; c < 64; c++) {
            float4 vv = *(const float4*)&Vs[c*68 + tx*4];
            float vr[4] = {vv.x, vv.y, vv.z, vv.w};
            #pragma unroll
            for (int i = 0; i < 4; i++) {
                float p = Ps[(ty*4 + i) * 68 + c];
                #pragma unroll
                for (int j = 0; j < 4; j++)
                    O[i][j] = fmaf(p, vr[j], O[i][j]);
            }
        }
        __syncthreads();
    }

    // Epilogue: normalize and write ctx[b][s][h*64+d]
    const int b = bh >> 4, h = bh & 15;
    #pragma unroll
    for (int i = 0; i < 4; i++) {
        int sg = row0 + ty*4 + i;
        float inv = 1.f / lrow[i];
        float4 o;
        o.x = O[i][0] * inv;
        o.y = O[i][1] * inv;
        o.z = O[i][2] * inv;
        o.w = O[i][3] * inv;
        *(float4*)&g_ctx[((size_t)(b * S_ + sg)) * E_ + h * D_ + tx*4] = o;
    }
}

// ---------------------------------------------------------------------------
// Launch: 3 QKV GEMMs -> flash attention -> output GEMM. Single default
// stream, graph-capturable (no sync, no alloc).
// ---------------------------------------------------------------------------
extern "C" void kernel_launch(void* const* d_in, const int* in_sizes, int n_in,
                              void* d_out, int out_size)
{
    const float* query = (const float*)d_in[0];
    const float* key   = (const float*)d_in[1];
    const float* value = (const float*)d_in[2];
    const float* qkvw  = (const float*)d_in[3];
    const float* qkvb  = (const float*)d_in[4];
    const float* projw = (const float*)d_in[5];
    const float* projb = (const float*)d_in[6];
    const float* mask  = (const float*)d_in[7];

    float *qp, *kp, *vp, *cp;
    cudaGetSymbolAddress((void**)&qp, g_q);
    cudaGetSymbolAddress((void**)&kp, g_k);
    cudaGetSymbolAddress((void**)&vp, g_v);
    cudaGetSymbolAddress((void**)&cp, g_ctx);

    dim3 gb(E_ / 128, M_ / 128);   // (8, 32)

    gemm_xwT<1><<<gb, 256>>>(query, qkvw,                 qkvb,          qp);
    gemm_xwT<1><<<gb, 256>>>(key,   qkvw + (size_t)E_*E_, qkvb + E_,     kp);
    gemm_xwT<1><<<gb, 256>>>(value, qkvw + (size_t)2*E_*E_, qkvb + 2*E_, vp);

    size_t shmem = (size_t)(4*64*68 + 2*64*16) * sizeof(float);  // 77824 B
    cudaFuncSetAttribute(flash_attn, cudaFuncAttributeMaxDynamicSharedMemorySize, (int)shmem);
    flash_attn<<<dim3(S_/64, B_*H_), 256, shmem>>>(mask);

    gemm_xwT<0><<<gb, 256>>>(cp, projw, projb, (float*)d_out);
}

// round 4
// speedup vs baseline: 2.2483x; 2.2483x over previous
#include <cuda_runtime.h>
#include <cuda_bf16.h>
#include <math.h>

#define B_ 2
#define S_ 2048
#define E_ 1024
#define H_ 16
#define D_ 64
#define M_ (B_*S_)

// Scratch (__device__ globals: allocation-free rule)
__device__ float g_q[B_*H_*S_*D_];    // [B,H,S,D]
__device__ float g_k[B_*H_*S_*D_];
__device__ float g_v[B_*H_*S_*D_];
__device__ float g_ctx[B_*S_*E_];     // [B,S,E]

// ---------------------------------------------------------------------------
// Helpers: bf16 split/pack, ldmatrix, mma
// ---------------------------------------------------------------------------
__device__ __forceinline__ unsigned cvta_s(const void* p) {
    return (unsigned)__cvta_generic_to_shared(p);
}

__device__ __forceinline__ unsigned pk2(__nv_bfloat16 a, __nv_bfloat16 b) {
    return (unsigned)__bfloat16_as_ushort(a) | ((unsigned)__bfloat16_as_ushort(b) << 16);
}

// x = hi + lo (hi rounds to bf16, lo = residual in bf16). Pack pairs (low half = first arg).
__device__ __forceinline__ void splitpk(float x, float y, unsigned& h, unsigned& l) {
    __nv_bfloat16 hx = __float2bfloat16_rn(x);
    __nv_bfloat16 hy = __float2bfloat16_rn(y);
    float rx = x - __bfloat162float(hx);
    float ry = y - __bfloat162float(hy);
    h = pk2(hx, hy);
    l = pk2(__float2bfloat16_rn(rx), __float2bfloat16_rn(ry));
}

// Split a float4 and store 4 hi bf16 + 4 lo bf16 at element offset 'off' (multiple of 4).
__device__ __forceinline__ void split_store4(__nv_bfloat16* Hb, __nv_bfloat16* Lb,
                                             int off, float4 v) {
    unsigned h0, l0, h1, l1;
    splitpk(v.x, v.y, h0, l0);
    splitpk(v.z, v.w, h1, l1);
    *(uint2*)(Hb + off) = make_uint2(h0, h1);
    *(uint2*)(Lb + off) = make_uint2(l0, l1);
}

__device__ __forceinline__ void ldsm4(unsigned& r0, unsigned& r1, unsigned& r2, unsigned& r3,
                                      unsigned a) {
    asm volatile("ldmatrix.sync.aligned.m8n8.x4.shared.b16 {%0,%1,%2,%3}, [%4];"
                 : "=r"(r0), "=r"(r1), "=r"(r2), "=r"(r3) : "r"(a));
}
__device__ __forceinline__ void ldsm4t(unsigned& r0, unsigned& r1, unsigned& r2, unsigned& r3,
                                       unsigned a) {
    asm volatile("ldmatrix.sync.aligned.m8n8.x4.trans.shared.b16 {%0,%1,%2,%3}, [%4];"
                 : "=r"(r0), "=r"(r1), "=r"(r2), "=r"(r3) : "r"(a));
}

__device__ __forceinline__ void mma16816(float* c,
                                         unsigned a0, unsigned a1, unsigned a2, unsigned a3,
                                         unsigned b0, unsigned b1) {
    asm volatile(
        "mma.sync.aligned.m16n8k16.row.col.f32.bf16.bf16.f32 "
        "{%0,%1,%2,%3}, {%4,%5,%6,%7}, {%8,%9}, {%0,%1,%2,%3};"
        : "+f"(c[0]), "+f"(c[1]), "+f"(c[2]), "+f"(c[3])
        : "r"(a0), "r"(a1), "r"(a2), "r"(a3), "r"(b0), "r"(b1));
}

// ---------------------------------------------------------------------------
// GEMM: C[m][n] = sum_k X[m][k]*W[n][k] + bias[n], K=1024. bf16x3 tensor core.
// Tile 128m x 64n x 32k. 8 warps: wm in {0..3} (32-row strips), wn in {0,1}
// (32-col strips). Per warp: 2 m16 tiles x 4 n8 tiles.
// QKV=1: n spans [0,3072): selects X/out by n>>10, scatters out to [B,H,S,D].
// QKV=0: plain row-major out.
// ---------------------------------------------------------------------------
template<int QKV>
__global__ void __launch_bounds__(256) gemm3(
    const float* __restrict__ X0, const float* __restrict__ X1, const float* __restrict__ X2,
    const float* __restrict__ W, const float* __restrict__ bias,
    float* __restrict__ O0, float* __restrict__ O1, float* __restrict__ O2)
{
    __shared__ __align__(16) __nv_bfloat16 AH[128 * 40];
    __shared__ __align__(16) __nv_bfloat16 AL[128 * 40];
    __shared__ __align__(16) __nv_bfloat16 BH[64 * 40];
    __shared__ __align__(16) __nv_bfloat16 BL[64 * 40];

    const int tid = threadIdx.x, lane = tid & 31, wid = tid >> 5;
    const int wm = wid & 3, wn = wid >> 2;
    const int m0 = blockIdx.y * 128;
    const int n0 = blockIdx.x * 64;

    const float* X;
    float* Ob;
    int sel = 0;
    if (QKV) {
        sel = n0 >> 10;
        X  = (sel == 0) ? X0 : ((sel == 1) ? X1 : X2);
        Ob = (sel == 0) ? O0 : ((sel == 1) ? O1 : O2);
    } else {
        X = X0; Ob = O0;
    }

    // Global load mapping: A 128x32 floats = 1024 float4 (4/thread), B 64x32 = 512 (2/thread)
    const float* ap[4]; int ao[4];
    #pragma unroll
    for (int i = 0; i < 4; i++) {
        int idx = tid + 256 * i;
        int r = idx >> 3, f = idx & 7;
        ap[i] = X + (size_t)(m0 + r) * E_ + f * 4;
        ao[i] = r * 40 + f * 4;
    }
    const float* bp[2]; int bo[2];
    #pragma unroll
    for (int i = 0; i < 2; i++) {
        int idx = tid + 256 * i;
        int r = idx >> 3, f = idx & 7;
        bp[i] = W + (size_t)(n0 + r) * E_ + f * 4;
        bo[i] = r * 40 + f * 4;
    }

    float4 pa[4], pb[2];
    #pragma unroll
    for (int i = 0; i < 4; i++) pa[i] = *(const float4*)(ap[i]);
    #pragma unroll
    for (int i = 0; i < 2; i++) pb[i] = *(const float4*)(bp[i]);

    float acc[2][4][4];
    #pragma unroll
    for (int mi = 0; mi < 2; mi++)
        #pragma unroll
        for (int nt = 0; nt < 4; nt++)
            #pragma unroll
            for (int q = 0; q < 4; q++) acc[mi][nt][q] = 0.f;

    const unsigned aAH = cvta_s(AH), aAL = cvta_s(AL);
    const unsigned aBH = cvta_s(BH), aBL = cvta_s(BL);
    const int arow = wm * 32 + (lane & 15);          // + mi*16
    const int ak8  = (lane >> 4) * 8;
    const int brow = wn * 32 + (lane >> 4) * 8 + (lane & 7);  // + p*16
    const int bk8  = ((lane >> 3) & 1) * 8;

    for (int k0 = 0; k0 < E_; k0 += 32) {
        #pragma unroll
        for (int i = 0; i < 4; i++) split_store4(AH, AL, ao[i], pa[i]);
        #pragma unroll
        for (int i = 0; i < 2; i++) split_store4(BH, BL, bo[i], pb[i]);
        __syncthreads();

        if (k0 + 32 < E_) {
            #pragma unroll
            for (int i = 0; i < 4; i++) pa[i] = *(const float4*)(ap[i] + k0 + 32);
            #pragma unroll
            for (int i = 0; i < 2; i++) pb[i] = *(const float4*)(bp[i] + k0 + 32);
        }

        #pragma unroll
        for (int ks = 0; ks < 2; ks++) {
            unsigned ah[2][4], al[2][4], bh4[2][4], bl4[2][4];
            #pragma unroll
            for (int mi = 0; mi < 2; mi++) {
                int off = ((arow + mi * 16) * 40 + ks * 16 + ak8) * 2;
                ldsm4(ah[mi][0], ah[mi][1], ah[mi][2], ah[mi][3], aAH + off);
                ldsm4(al[mi][0], al[mi][1], al[mi][2], al[mi][3], aAL + off);
            }
            #pragma unroll
            for (int p = 0; p < 2; p++) {
                int off = ((brow + p * 16) * 40 + ks * 16 + bk8) * 2;
                ldsm4(bh4[p][0], bh4[p][1], bh4[p][2], bh4[p][3], aBH + off);
                ldsm4(bl4[p][0], bl4[p][1], bl4[p][2], bl4[p][3], aBL + off);
            }
            #pragma unroll
            for (int mi = 0; mi < 2; mi++)
                #pragma unroll
                for (int nt = 0; nt < 4; nt++) {
                    int p = nt >> 1, u = (nt & 1) * 2;
                    mma16816(acc[mi][nt], ah[mi][0], ah[mi][1], ah[mi][2], ah[mi][3],
                             bh4[p][u], bh4[p][u + 1]);
                    mma16816(acc[mi][nt], ah[mi][0], ah[mi][1], ah[mi][2], ah[mi][3],
                             bl4[p][u], bl4[p][u + 1]);
                    mma16816(acc[mi][nt], al[mi][0], al[mi][1], al[mi][2], al[mi][3],
                             bh4[p][u], bh4[p][u + 1]);
                }
        }
        __syncthreads();
    }

    // Epilogue
    #pragma unroll
    for (int mi = 0; mi < 2; mi++) {
        int mr = m0 + wm * 32 + mi * 16 + (lane >> 2);
        #pragma unroll
        for (int nt = 0; nt < 4; nt++) {
            int c = n0 + wn * 32 + nt * 8 + (lane & 3) * 2;
            float b0 = bias[c], b1 = bias[c + 1];
            float2 v0 = make_float2(acc[mi][nt][0] + b0, acc[mi][nt][1] + b1);
            float2 v1 = make_float2(acc[mi][nt][2] + b0, acc[mi][nt][3] + b1);
            if (QKV) {
                int nl = c - (sel << 10);
                int h = nl >> 6, d = nl & 63;
                int bb = mr >> 11, s = mr & (S_ - 1);
                size_t base = ((size_t)(bb * H_ + h) * S_ + s) * D_ + d;
                *(float2*)(Ob + base)          = v0;
                *(float2*)(Ob + base + 8 * D_) = v1;   // row mr+8 (same 2048-block)
            } else {
                *(float2*)(Ob + (size_t)mr * E_ + c)       = v0;
                *(float2*)(Ob + (size_t)(mr + 8) * E_ + c) = v1;
            }
        }
    }
}

// ---------------------------------------------------------------------------
// Flash attention with mma.sync bf16x3. BR=128, BC=64, D=64, 256 threads.
// Each warp owns a 16-row strip of the 128-row Q block -> softmax stats are
// warp-local (quad shuffles only). V in natural [c][d] layout, B-fragments
// via ldmatrix.trans. P fragments built directly from score accumulators.
// ---------------------------------------------------------------------------
__global__ void __launch_bounds__(256) flash_mma(const float* __restrict__ mask)
{
    extern __shared__ __align__(16) __nv_bfloat16 sm[];
    __nv_bfloat16* QH = sm;              // [128][72]
    __nv_bfloat16* QL = QH + 128 * 72;
    __nv_bfloat16* KH = QL + 128 * 72;   // [64][72]
    __nv_bfloat16* KL = KH + 64 * 72;
    __nv_bfloat16* VH = KL + 64 * 72;    // [64][72]
    __nv_bfloat16* VL = VH + 64 * 72;

    const int tid = threadIdx.x, lane = tid & 31, wid = tid >> 5;
    const int bh = blockIdx.y;                 // b*H + h
    const int row0 = blockIdx.x * 128;

    const float* qb = g_q + ((size_t)bh * S_ + row0) * D_;
    const float* kb = g_k + (size_t)bh * S_ * D_;
    const float* vb = g_v + (size_t)bh * S_ * D_;

    // Load Q (pre-scaled by 1/sqrt(D)) -> hi/lo smem
    #pragma unroll
    for (int i = 0; i < 8; i++) {
        int idx = tid + 256 * i;
        int r = idx >> 4, f = idx & 15;
        float4 v = *(const float4*)(qb + (size_t)r * D_ + f * 4);
        v.x *= 0.125f; v.y *= 0.125f; v.z *= 0.125f; v.w *= 0.125f;
        split_store4(QH, QL, r * 72 + f * 4, v);
    }

    float O[8][4];
    #pragma unroll
    for (int nt = 0; nt < 8; nt++)
        #pragma unroll
        for (int q = 0; q < 4; q++) O[nt][q] = 0.f;
    float mr0 = -1e30f, mr1 = -1e30f, lr0 = 0.f, lr1 = 0.f;

    const unsigned aQH = cvta_s(QH), aQL = cvta_s(QL);
    const unsigned aKH = cvta_s(KH), aKL = cvta_s(KL);
    const unsigned aVH = cvta_s(VH), aVL = cvta_s(VL);
    const int qrow = wid * 16 + (lane & 15);
    const int qk8  = (lane >> 4) * 8;
    const int krow = (lane >> 4) * 8 + (lane & 7);       // + p*16
    const int kk8  = ((lane >> 3) & 1) * 8;
    const int vrow = ((lane >> 3) & 1) * 8 + (lane & 7); // + ks*16
    const int vc8  = (lane >> 4) * 8;                    // + p*16

    const int r1 = row0 + wid * 16 + (lane >> 2);        // this thread's first row
    const float* mrow1 = mask + (size_t)r1 * S_;
    const float* mrow2 = mrow1 + 8 * S_;

    for (int t = 0; t < S_ / 64; t++) {
        // Load K, V tiles (64x64 each) -> hi/lo smem
        #pragma unroll
        for (int i = 0; i < 4; i++) {
            int idx = tid + 256 * i;
            int r = idx >> 4, f = idx & 15;
            size_t g = (size_t)(t * 64 + r) * D_ + f * 4;
            split_store4(KH, KL, r * 72 + f * 4, *(const float4*)(kb + g));
            split_store4(VH, VL, r * 72 + f * 4, *(const float4*)(vb + g));
        }
        __syncthreads();

        // ---- S = Q K^T (bf16x3) ----
        float sa[8][4];
        #pragma unroll
        for (int nt = 0; nt < 8; nt++)
            #pragma unroll
            for (int q = 0; q < 4; q++) sa[nt][q] = 0.f;

        #pragma unroll
        for (int ks = 0; ks < 4; ks++) {
            unsigned ah[4], al4[4];
            int aoff = (qrow * 72 + ks * 16 + qk8) * 2;
            ldsm4(ah[0], ah[1], ah[2], ah[3], aQH + aoff);
            ldsm4(al4[0], al4[1], al4[2], al4[3], aQL + aoff);
            unsigned bh4[4][4], bl4[4][4];
            #pragma unroll
            for (int p = 0; p < 4; p++) {
                int boff = ((krow + p * 16) * 72 + ks * 16 + kk8) * 2;
                ldsm4(bh4[p][0], bh4[p][1], bh4[p][2], bh4[p][3], aKH + boff);
                ldsm4(bl4[p][0], bl4[p][1], bl4[p][2], bl4[p][3], aKL + boff);
            }
            #pragma unroll
            for (int nt = 0; nt < 8; nt++) {
                int p = nt >> 1, u = (nt & 1) * 2;
                mma16816(sa[nt], ah[0], ah[1], ah[2], ah[3], bh4[p][u], bh4[p][u + 1]);
                mma16816(sa[nt], ah[0], ah[1], ah[2], ah[3], bl4[p][u], bl4[p][u + 1]);
                mma16816(sa[nt], al4[0], al4[1], al4[2], al4[3], bh4[p][u], bh4[p][u + 1]);
            }
        }

        // ---- mask + online softmax (warp-local) ----
        int cb = t * 64 + (lane & 3) * 2;
        float mx0 = -1e30f, mx1 = -1e30f;
        #pragma unroll
        for (int nt = 0; nt < 8; nt++) {
            float2 m1 = *(const float2*)(mrow1 + cb + nt * 8);
            float2 m2 = *(const float2*)(mrow2 + cb + nt * 8);
            sa[nt][0] += m1.x; sa[nt][1] += m1.y;
            sa[nt][2] += m2.x; sa[nt][3] += m2.y;
            mx0 = fmaxf(mx0, fmaxf(sa[nt][0], sa[nt][1]));
            mx1 = fmaxf(mx1, fmaxf(sa[nt][2], sa[nt][3]));
        }
        mx0 = fmaxf(mx0, __shfl_xor_sync(0xffffffffu, mx0, 1));
        mx0 = fmaxf(mx0, __shfl_xor_sync(0xffffffffu, mx0, 2));
        mx1 = fmaxf(mx1, __shfl_xor_sync(0xffffffffu, mx1, 1));
        mx1 = fmaxf(mx1, __shfl_xor_sync(0xffffffffu, mx1, 2));

        float mn0 = fmaxf(mr0, mx0), mn1 = fmaxf(mr1, mx1);
        float a0 = __expf(mr0 - mn0), a1 = __expf(mr1 - mn1);
        mr0 = mn0; mr1 = mn1;

        float s0 = 0.f, s1 = 0.f;
        #pragma unroll
        for (int nt = 0; nt < 8; nt++) {
            sa[nt][0] = __expf(sa[nt][0] - mn0); s0 += sa[nt][0];
            sa[nt][1] = __expf(sa[nt][1] - mn0); s0 += sa[nt][1];
            sa[nt][2] = __expf(sa[nt][2] - mn1); s1 += sa[nt][2];
            sa[nt][3] = __expf(sa[nt][3] - mn1); s1 += sa[nt][3];
        }
        s0 += __shfl_xor_sync(0xffffffffu, s0, 1);
        s0 += __shfl_xor_sync(0xffffffffu, s0, 2);
        s1 += __shfl_xor_sync(0xffffffffu, s1, 1);
        s1 += __shfl_xor_sync(0xffffffffu, s1, 2);
        lr0 = lr0 * a0 + s0;
        lr1 = lr1 * a1 + s1;
        #pragma unroll
        for (int nt = 0; nt < 8; nt++) {
            O[nt][0] *= a0; O[nt][1] *= a0;
            O[nt][2] *= a1; O[nt][3] *= a1;
        }

        // ---- O += P V (bf16x3; P frags straight from accumulators) ----
        #pragma unroll
        for (int ks = 0; ks < 4; ks++) {
            int j0 = 2 * ks, j1 = j0 + 1;
            unsigned ph0, ph1, ph2, ph3, pl0, pl1, pl2, pl3;
            splitpk(sa[j0][0], sa[j0][1], ph0, pl0);
            splitpk(sa[j0][2], sa[j0][3], ph1, pl1);
            splitpk(sa[j1][0], sa[j1][1], ph2, pl2);
            splitpk(sa[j1][2], sa[j1][3], ph3, pl3);
            unsigned vh4[4][4], vl4[4][4];
            #pragma unroll
            for (int p = 0; p < 4; p++) {
                int voff = ((vrow + ks * 16) * 72 + vc8 + p * 16) * 2;
                ldsm4t(vh4[p][0], vh4[p][1], vh4[p][2], vh4[p][3], aVH + voff);
                ldsm4t(vl4[p][0], vl4[p][1], vl4[p][2], vl4[p][3], aVL + voff);
            }
            #pragma unroll
            for (int nt = 0; nt < 8; nt++) {
                int p = nt >> 1, u = (nt & 1) * 2;
                mma16816(O[nt], ph0, ph1, ph2, ph3, vh4[p][u], vh4[p][u + 1]);
                mma16816(O[nt], ph0, ph1, ph2, ph3, vl4[p][u], vl4[p][u + 1]);
                mma16816(O[nt], pl0, pl1, pl2, pl3, vh4[p][u], vh4[p][u + 1]);
            }
        }
        __syncthreads();
    }

    // Epilogue: normalize, write ctx [B,S,E]
    float i0 = 1.f / lr0, i1 = 1.f / lr1;
    int b = bh >> 4, h = bh & 15;
    float* o1 = g_ctx + ((size_t)(b * S_ + r1)) * E_ + h * D_ + (lane & 3) * 2;
    float* o2 = o1 + 8 * E_;
    #pragma unroll
    for (int nt = 0; nt < 8; nt++) {
        *(float2*)(o1 + nt * 8) = make_float2(O[nt][0] * i0, O[nt][1] * i0);
        *(float2*)(o2 + nt * 8) = make_float2(O[nt][2] * i1, O[nt][3] * i1);
    }
}

// ---------------------------------------------------------------------------
// Launch: fused QKV GEMM -> flash attention -> output GEMM.
// ---------------------------------------------------------------------------
extern "C" void kernel_launch(void* const* d_in, const int* in_sizes, int n_in,
                              void* d_out, int out_size)
{
    const float* query = (const float*)d_in[0];
    const float* key   = (const float*)d_in[1];
    const float* value = (const float*)d_in[2];
    const float* qkvw  = (const float*)d_in[3];
    const float* qkvb  = (const float*)d_in[4];
    const float* projw = (const float*)d_in[5];
    const float* projb = (const float*)d_in[6];
    const float* mask  = (const float*)d_in[7];

    float *qp, *kp, *vp, *cp;
    cudaGetSymbolAddress((void**)&qp, g_q);
    cudaGetSymbolAddress((void**)&kp, g_k);
    cudaGetSymbolAddress((void**)&vp, g_v);
    cudaGetSymbolAddress((void**)&cp, g_ctx);

    // Fused QKV projection: n in [0,3072)
    gemm3<1><<<dim3(48, 32), 256>>>(query, key, value, qkvw, qkvb, qp, kp, vp);

    // Flash attention
    size_t shmem = (size_t)(2 * 128 * 72 + 4 * 64 * 72) * sizeof(__nv_bfloat16); // 73728
    cudaFuncSetAttribute(flash_mma, cudaFuncAttributeMaxDynamicSharedMemorySize, (int)shmem);
    flash_mma<<<dim3(S_ / 128, B_ * H_), 256, shmem>>>(mask);

    // Output projection
    gemm3<0><<<dim3(16, 32), 256>>>(cp, nullptr, nullptr, projw, projb,
                                    (float*)d_out, nullptr, nullptr);
}

// round 7
// speedup vs baseline: 2.4850x; 1.1053x over previous
#include <cuda_runtime.h>
#include <cuda_bf16.h>

#define B_ 2
#define S_ 2048
#define E_ 1024
#define H_ 16
#define D_ 64
#define M_ 4096
#define K_ 1024

// ---------------------------------------------------------------------------
// Scratch (__device__ globals: allocation-free rule). All bf16 hi/lo pairs.
// ---------------------------------------------------------------------------
__device__ __align__(256) __nv_bfloat16 g_xh[(size_t)3*M_*K_];  // split q/k/v inputs
__device__ __align__(256) __nv_bfloat16 g_xl[(size_t)3*M_*K_];
__device__ __align__(256) __nv_bfloat16 g_wh[(size_t)4*K_*K_];  // qkvw(3M) + projw(1M)
__device__ __align__(256) __nv_bfloat16 g_wl[(size_t)4*K_*K_];
__device__ __align__(256) __nv_bfloat16 g_sh[(size_t)3*B_*H_*S_*D_]; // split q/k/v heads
__device__ __align__(256) __nv_bfloat16 g_sl[(size_t)3*B_*H_*S_*D_];
__device__ __align__(256) __nv_bfloat16 g_ch[(size_t)M_*E_];    // split ctx
__device__ __align__(256) __nv_bfloat16 g_cl[(size_t)M_*E_];

// ---------------------------------------------------------------------------
// Helpers
// ---------------------------------------------------------------------------
__device__ __forceinline__ unsigned cvta_s(const void* p) {
    return (unsigned)__cvta_generic_to_shared(p);
}
__device__ __forceinline__ unsigned pk2(__nv_bfloat16 a, __nv_bfloat16 b) {
    return (unsigned)__bfloat16_as_ushort(a) | ((unsigned)__bfloat16_as_ushort(b) << 16);
}
__device__ __forceinline__ void splitpk(float x, float y, unsigned& h, unsigned& l) {
    __nv_bfloat16 hx = __float2bfloat16_rn(x);
    __nv_bfloat16 hy = __float2bfloat16_rn(y);
    float rx = x - __bfloat162float(hx);
    float ry = y - __bfloat162float(hy);
    h = pk2(hx, hy);
    l = pk2(__float2bfloat16_rn(rx), __float2bfloat16_rn(ry));
}
__device__ __forceinline__ void ldsm4(unsigned& r0, unsigned& r1, unsigned& r2, unsigned& r3,
                                      unsigned a) {
    asm volatile("ldmatrix.sync.aligned.m8n8.x4.shared.b16 {%0,%1,%2,%3}, [%4];"
                 : "=r"(r0), "=r"(r1), "=r"(r2), "=r"(r3) : "r"(a));
}
__device__ __forceinline__ void ldsm4t(unsigned& r0, unsigned& r1, unsigned& r2, unsigned& r3,
                                       unsigned a) {
    asm volatile("ldmatrix.sync.aligned.m8n8.x4.trans.shared.b16 {%0,%1,%2,%3}, [%4];"
                 : "=r"(r0), "=r"(r1), "=r"(r2), "=r"(r3) : "r"(a));
}
__device__ __forceinline__ void mma16816(float* c,
                                         unsigned a0, unsigned a1, unsigned a2, unsigned a3,
                                         unsigned b0, unsigned b1) {
    asm volatile(
        "mma.sync.aligned.m16n8k16.row.col.f32.bf16.bf16.f32 "
        "{%0,%1,%2,%3}, {%4,%5,%6,%7}, {%8,%9}, {%0,%1,%2,%3};"
        : "+f"(c[0]), "+f"(c[1]), "+f"(c[2]), "+f"(c[3])
        : "r"(a0), "r"(a1), "r"(a2), "r"(a3), "r"(b0), "r"(b1));
}
__device__ __forceinline__ void cpa16(unsigned dst, const void* src) {
    asm volatile("cp.async.cg.shared.global [%0], [%1], 16;" :: "r"(dst), "l"(src));
}
__device__ __forceinline__ void cpa_commit() {
    asm volatile("cp.async.commit_group;" ::: "memory");
}
template<int N>
__device__ __forceinline__ void cpa_wait() {
    asm volatile("cp.async.wait_group %0;" :: "n"(N) : "memory");
}

// ---------------------------------------------------------------------------
// Split pass: fp32 -> bf16 hi/lo for q/k/v inputs + qkv weight + proj weight.
// 4M float4 total.
// ---------------------------------------------------------------------------
__global__ void __launch_bounds__(256) split_all(
    const float* __restrict__ q, const float* __restrict__ k, const float* __restrict__ v,
    const float* __restrict__ qkvw, const float* __restrict__ projw)
{
    size_t i4 = (size_t)blockIdx.x * 256 + threadIdx.x;
    const size_t XQ = (size_t)M_ * K_ / 4;          // 1M float4 per x input
    const size_t WQ = (size_t)3 * K_ * K_ / 4;      // 768K float4 qkvw
    const float* src; __nv_bfloat16 *dh, *dl; size_t o;
    if (i4 < 3 * XQ) {
        size_t sel = i4 / XQ; o = i4 - sel * XQ;
        src = (sel == 0) ? q : ((sel == 1) ? k : v);
        dh = g_xh + sel * (size_t)M_ * K_;
        dl = g_xl + sel * (size_t)M_ * K_;
    } else if (i4 < 3 * XQ + WQ) {
        o = i4 - 3 * XQ; src = qkvw; dh = g_wh; dl = g_wl;
    } else {
        o = i4 - 3 * XQ - WQ; src = projw;
        dh = g_wh + (size_t)3 * K_ * K_;
        dl = g_wl + (size_t)3 * K_ * K_;
    }
    float4 x = *((const float4*)src + o);
    unsigned h0, l0, h1, l1;
    splitpk(x.x, x.y, h0, l0);
    splitpk(x.z, x.w, h1, l1);
    *(uint2*)(dh + o * 4) = make_uint2(h0, h1);
    *(uint2*)(dl + o * 4) = make_uint2(l0, l1);
}

// ---------------------------------------------------------------------------
// bf16x3 GEMM on pre-split inputs. C[m][n] = sum_k A[m][k]*W[n][k] (+bias).
// CTA 128x128, warp tile 32x64 (8 warps: wm 0..3, wn 0..1). K-chunk 64,
// cp.async double-buffered (2 x 72KB). Rows padded to 72 elems (144B).
// QKV=1: A selected by n0>>10; epilogue -> g_sh/g_sl per-head split
//        (q scaled 1/8, bias added).  QKV=0: fp32 out + bias.
// ---------------------------------------------------------------------------
#define GEMM_SMEM (2 * 4 * 128 * 72 * 2)   // 147456 B

template<int QKV>
__global__ void __launch_bounds__(256, 1) gemm_bf16(
    const __nv_bfloat16* __restrict__ Ah0, const __nv_bfloat16* __restrict__ Al0,
    const __nv_bfloat16* __restrict__ Wh, const __nv_bfloat16* __restrict__ Wl,
    const float* __restrict__ bias, float* __restrict__ out)
{
    extern __shared__ __align__(1024) __nv_bfloat16 smg[];
    const unsigned sb = cvta_s(smg);

    const int tid = threadIdx.x, lane = tid & 31, wid = tid >> 5;
    const int wm = wid & 3, wn = wid >> 2;
    const int m0 = blockIdx.y * 128, n0 = blockIdx.x * 128;

    const __nv_bfloat16* Ah = Ah0;
    const __nv_bfloat16* Al = Al0;
    int sel = 0;
    if (QKV) {
        sel = n0 >> 10;
        Ah += (size_t)sel * M_ * K_;
        Al += (size_t)sel * M_ * K_;
    }

    // cp.async mapping: per array 1024 chunks (128 rows x 8), 4 per thread.
    int rr[4], so[4];
    #pragma unroll
    for (int i = 0; i < 4; i++) {
        int idx = tid + 256 * i;
        rr[i] = idx >> 3;
        so[i] = (idx >> 3) * 144 + (idx & 7) * 16;   // smem byte offset in one array
    }
    // gmem elem offsets within row: (idx&7)*8
    int gf[4];
    #pragma unroll
    for (int i = 0; i < 4; i++) gf[i] = (tid + 256 * i & 7) * 8;

    // Buffer b base (bytes): b*73728; arrays Ah +0, Al +18432, Wh +36864, Wl +55296.

    // preload chunk 0 -> buf 0
    #pragma unroll
    for (int i = 0; i < 4; i++) {
        unsigned d = sb + so[i];
        const __nv_bfloat16* ga = Ah + (size_t)(m0 + rr[i]) * K_ + gf[i];
        const __nv_bfloat16* gal = Al + (size_t)(m0 + rr[i]) * K_ + gf[i];
        const __nv_bfloat16* gw = Wh + (size_t)(n0 + rr[i]) * K_ + gf[i];
        const __nv_bfloat16* gwl = Wl + (size_t)(n0 + rr[i]) * K_ + gf[i];
        cpa16(d,          ga);
        cpa16(d + 18432,  gal);
        cpa16(d + 36864,  gw);
        cpa16(d + 55296,  gwl);
    }
    cpa_commit();

    float acc[2][8][4];
    #pragma unroll
    for (int mi = 0; mi < 2; mi++)
        #pragma unroll
        for (int nt = 0; nt < 8; nt++)
            #pragma unroll
            for (int q = 0; q < 4; q++) acc[mi][nt][q] = 0.f;

    const int arow = wm * 32 + (lane & 15);     // +mi*16
    const int ak8  = (lane >> 4) * 8;
    const int brow = wn * 64 + (lane >> 4) * 8 + (lane & 7);   // +p*16
    const int bk8  = ((lane >> 3) & 1) * 8;

    const int NC = K_ / 64;   // 16
    for (int c = 0; c < NC; c++) {
        if (c + 1 < NC) {
            const unsigned bb = sb + ((c + 1) & 1) * 73728;
            const int ko = (c + 1) * 64;
            #pragma unroll
            for (int i = 0; i < 4; i++) {
                unsigned d = bb + so[i];
                cpa16(d,         Ah + (size_t)(m0 + rr[i]) * K_ + ko + gf[i]);
                cpa16(d + 18432, Al + (size_t)(m0 + rr[i]) * K_ + ko + gf[i]);
                cpa16(d + 36864, Wh + (size_t)(n0 + rr[i]) * K_ + ko + gf[i]);
                cpa16(d + 55296, Wl + (size_t)(n0 + rr[i]) * K_ + ko + gf[i]);
            }
            cpa_commit();
            cpa_wait<1>();
        } else {
            cpa_wait<0>();
        }
        __syncthreads();

        const unsigned ab = sb + (c & 1) * 73728;
        #pragma unroll
        for (int ks = 0; ks < 4; ks++) {
            unsigned ah[2][4], al[2][4];
            #pragma unroll
            for (int mi = 0; mi < 2; mi++) {
                unsigned off = ab + ((arow + mi * 16) * 72 + ks * 16 + ak8) * 2;
                ldsm4(ah[mi][0], ah[mi][1], ah[mi][2], ah[mi][3], off);
                ldsm4(al[mi][0], al[mi][1], al[mi][2], al[mi][3], off + 18432);
            }
            unsigned bh4[4][4], bl4[4][4];
            #pragma unroll
            for (int p = 0; p < 4; p++) {
                unsigned off = ab + 36864 + ((brow + p * 16) * 72 + ks * 16 + bk8) * 2;
                ldsm4(bh4[p][0], bh4[p][1], bh4[p][2], bh4[p][3], off);
                ldsm4(bl4[p][0], bl4[p][1], bl4[p][2], bl4[p][3], off + 18432);
            }
            #pragma unroll
            for (int mi = 0; mi < 2; mi++)
                #pragma unroll
                for (int nt = 0; nt < 8; nt++) {
                    int p = nt >> 1, u = (nt & 1) * 2;
                    mma16816(acc[mi][nt], ah[mi][0], ah[mi][1], ah[mi][2], ah[mi][3],
                             bh4[p][u], bh4[p][u + 1]);
                    mma16816(acc[mi][nt], ah[mi][0], ah[mi][1], ah[mi][2], ah[mi][3],
                             bl4[p][u], bl4[p][u + 1]);
                    mma16816(acc[mi][nt], al[mi][0], al[mi][1], al[mi][2], al[mi][3],
                             bh4[p][u], bh4[p][u + 1]);
                }
        }
        __syncthreads();
    }

    // Epilogue
    #pragma unroll
    for (int mi = 0; mi < 2; mi++) {
        const int row = m0 + wm * 32 + mi * 16 + (lane >> 2);
        #pragma unroll
        for (int nt = 0; nt < 8; nt++) {
            const int cg = n0 + wn * 64 + nt * 8 + (lane & 3) * 2;
            float2 bv = *(const float2*)(bias + cg);
            if (QKV) {
                const float scl = (sel == 0) ? 0.125f : 1.0f;
                const int nl = cg - (sel << 10);
                const int h = nl >> 6, d = nl & 63;
                const int bb2 = row >> 11, s = row & (S_ - 1);
                size_t base = ((size_t)((sel * 32 + bb2 * H_ + h) * S_ + s)) * D_ + d;
                unsigned hw, lw;
                splitpk((acc[mi][nt][0] + bv.x) * scl, (acc[mi][nt][1] + bv.y) * scl, hw, lw);
                *(unsigned*)(g_sh + base) = hw;
                *(unsigned*)(g_sl + base) = lw;
                splitpk((acc[mi][nt][2] + bv.x) * scl, (acc[mi][nt][3] + bv.y) * scl, hw, lw);
                *(unsigned*)(g_sh + base + 8 * D_) = hw;
                *(unsigned*)(g_sl + base + 8 * D_) = lw;
            } else {
                *(float2*)(out + (size_t)row * E_ + cg) =
                    make_float2(acc[mi][nt][0] + bv.x, acc[mi][nt][1] + bv.y);
                *(float2*)(out + (size_t)(row + 8) * E_ + cg) =
                    make_float2(acc[mi][nt][2] + bv.x, acc[mi][nt][3] + bv.y);
            }
        }
    }
}

// ---------------------------------------------------------------------------
// Flash attention, bf16x3 mma.sync. BR=128, BC=64, 256 threads.
// Q fragments register-resident (loaded once); K/V pre-split bf16 hi/lo in
// gmem, cp.async double-buffered. Epilogue writes ctx pre-split (g_ch/g_cl).
// ---------------------------------------------------------------------------
#define FL_SMEM 73728

__global__ void __launch_bounds__(256, 1) flash_mma(const float* __restrict__ mask)
{
    extern __shared__ __align__(1024) __nv_bfloat16 smf[];
    const unsigned sb = cvta_s(smf);

    const int tid = threadIdx.x, lane = tid & 31, wid = tid >> 5;
    const int bh = blockIdx.y;                 // b*H + h
    const int row0 = blockIdx.x * 128;
    const int b = bh >> 4, h = bh & 15;

    const __nv_bfloat16* qhb = g_sh + ((size_t)bh * S_ + row0) * D_;
    const __nv_bfloat16* qlb = g_sl + ((size_t)bh * S_ + row0) * D_;
    const __nv_bfloat16* khb = g_sh + (size_t)(32 + bh) * S_ * D_;
    const __nv_bfloat16* klb = g_sl + (size_t)(32 + bh) * S_ * D_;
    const __nv_bfloat16* vhb = g_sh + (size_t)(64 + bh) * S_ * D_;
    const __nv_bfloat16* vlb = g_sl + (size_t)(64 + bh) * S_ * D_;

    // ---- Stage Q in smem (hi at 0, lo at elem 9216), then frags -> regs ----
    #pragma unroll
    for (int i = 0; i < 4; i++) {
        int idx = tid + 256 * i;
        int r = idx >> 3, f = (idx & 7) * 8;
        *(uint4*)&smf[r * 72 + f] = *(const uint4*)(qhb + (size_t)r * D_ + f);
        *(uint4*)&smf[9216 + r * 72 + f] = *(const uint4*)(qlb + (size_t)r * D_ + f);
    }
    __syncthreads();

    unsigned qh[4][4], ql[4][4];
    {
        const int qrow = wid * 16 + (lane & 15);
        const int qk8 = (lane >> 4) * 8;
        #pragma unroll
        for (int ks = 0; ks < 4; ks++) {
            unsigned off = sb + (qrow * 72 + ks * 16 + qk8) * 2;
            ldsm4(qh[ks][0], qh[ks][1], qh[ks][2], qh[ks][3], off);
            ldsm4(ql[ks][0], ql[ks][1], ql[ks][2], ql[ks][3], off + 18432);
        }
    }
    __syncthreads();   // Q reads done before KV pipeline overwrites smem

    // ---- KV cp.async mapping: per array 512 chunks (64 rows x 8), 2/thread ----
    int kr[2], kso[2], kgf[2];
    #pragma unroll
    for (int i = 0; i < 2; i++) {
        int idx = tid + 256 * i;
        kr[i] = idx >> 3;
        kso[i] = (idx >> 3) * 144 + (idx & 7) * 16;
        kgf[i] = (idx & 7) * 8;
    }
    // buffer base (bytes): buf*36864; KH +0, KL +9216, VH +18432, VL +27648

    // preload t=0 -> buf 0
    #pragma unroll
    for (int i = 0; i < 2; i++) {
        unsigned d = sb + kso[i];
        size_t g = (size_t)kr[i] * D_ + kgf[i];
        cpa16(d,         khb + g);
        cpa16(d + 9216,  klb + g);
        cpa16(d + 18432, vhb + g);
        cpa16(d + 27648, vlb + g);
    }
    cpa_commit();

    float O[8][4];
    #pragma unroll
    for (int nt = 0; nt < 8; nt++)
        #pragma unroll
        for (int q = 0; q < 4; q++) O[nt][q] = 0.f;
    float mr0 = -1e30f, mr1 = -1e30f, lr0 = 0.f, lr1 = 0.f;

    const int krow = (lane >> 4) * 8 + (lane & 7);       // + p*16
    const int kk8  = ((lane >> 3) & 1) * 8;
    const int vrow = ((lane >> 3) & 1) * 8 + (lane & 7); // + ks*16
    const int vc8  = (lane >> 4) * 8;                    // + p*16

    const int r1 = row0 + wid * 16 + (lane >> 2);
    const float* mrow1 = mask + (size_t)r1 * S_;
    const float* mrow2 = mrow1 + 8 * S_;

    const int NT = S_ / 64;   // 32
    for (int t = 0; t < NT; t++) {
        if (t + 1 < NT) {
            const unsigned bb = sb + ((t + 1) & 1) * 36864;
            #pragma unroll
            for (int i = 0; i < 2; i++) {
                unsigned d = bb + kso[i];
                size_t g = (size_t)((t + 1) * 64 + kr[i]) * D_ + kgf[i];
                cpa16(d,         khb + g);
                cpa16(d + 9216,  klb + g);
                cpa16(d + 18432, vhb + g);
                cpa16(d + 27648, vlb + g);
            }
            cpa_commit();
            cpa_wait<1>();
        } else {
            cpa_wait<0>();
        }
        __syncthreads();

        const unsigned kbb = sb + (t & 1) * 36864;
        const unsigned vbb = kbb + 18432;

        // ---- S = Q K^T ----
        float sa[8][4];
        #pragma unroll
        for (int nt = 0; nt < 8; nt++)
            #pragma unroll
            for (int q = 0; q < 4; q++) sa[nt][q] = 0.f;

        #pragma unroll
        for (int ks = 0; ks < 4; ks++) {
            unsigned bh4[4][4], bl4[4][4];
            #pragma unroll
            for (int p = 0; p < 4; p++) {
                unsigned off = kbb + ((krow + p * 16) * 72 + ks * 16 + kk8) * 2;
                ldsm4(bh4[p][0], bh4[p][1], bh4[p][2], bh4[p][3], off);
                ldsm4(bl4[p][0], bl4[p][1], bl4[p][2], bl4[p][3], off + 9216);
            }
            #pragma unroll
            for (int nt = 0; nt < 8; nt++) {
                int p = nt >> 1, u = (nt & 1) * 2;
                mma16816(sa[nt], qh[ks][0], qh[ks][1], qh[ks][2], qh[ks][3],
                         bh4[p][u], bh4[p][u + 1]);
                mma16816(sa[nt], qh[ks][0], qh[ks][1], qh[ks][2], qh[ks][3],
                         bl4[p][u], bl4[p][u + 1]);
                mma16816(sa[nt], ql[ks][0], ql[ks][1], ql[ks][2], ql[ks][3],
                         bh4[p][u], bh4[p][u + 1]);
            }
        }

        // ---- mask + online softmax (warp-local) ----
        int cb = t * 64 + (lane & 3) * 2;
        float mx0 = -1e30f, mx1 = -1e30f;
        #pragma unroll
        for (int nt = 0; nt < 8; nt++) {
            float2 m1 = *(const float2*)(mrow1 + cb + nt * 8);
            float2 m2 = *(const float2*)(mrow2 + cb + nt * 8);
            sa[nt][0] += m1.x; sa[nt][1] += m1.y;
            sa[nt][2] += m2.x; sa[nt][3] += m2.y;
            mx0 = fmaxf(mx0, fmaxf(sa[nt][0], sa[nt][1]));
            mx1 = fmaxf(mx1, fmaxf(sa[nt][2], sa[nt][3]));
        }
        mx0 = fmaxf(mx0, __shfl_xor_sync(0xffffffffu, mx0, 1));
        mx0 = fmaxf(mx0, __shfl_xor_sync(0xffffffffu, mx0, 2));
        mx1 = fmaxf(mx1, __shfl_xor_sync(0xffffffffu, mx1, 1));
        mx1 = fmaxf(mx1, __shfl_xor_sync(0xffffffffu, mx1, 2));

        float mn0 = fmaxf(mr0, mx0), mn1 = fmaxf(mr1, mx1);
        float a0 = __expf(mr0 - mn0), a1 = __expf(mr1 - mn1);
        mr0 = mn0; mr1 = mn1;

        float s0 = 0.f, s1 = 0.f;
        #pragma unroll
        for (int nt = 0; nt < 8; nt++) {
            sa[nt][0] = __expf(sa[nt][0] - mn0); s0 += sa[nt][0];
            sa[nt][1] = __expf(sa[nt][1] - mn0); s0 += sa[nt][1];
            sa[nt][2] = __expf(sa[nt][2] - mn1); s1 += sa[nt][2];
            sa[nt][3] = __expf(sa[nt][3] - mn1); s1 += sa[nt][3];
        }
        s0 += __shfl_xor_sync(0xffffffffu, s0, 1);
        s0 += __shfl_xor_sync(0xffffffffu, s0, 2);
        s1 += __shfl_xor_sync(0xffffffffu, s1, 1);
        s1 += __shfl_xor_sync(0xffffffffu, s1, 2);
        lr0 = lr0 * a0 + s0;
        lr1 = lr1 * a1 + s1;
        #pragma unroll
        for (int nt = 0; nt < 8; nt++) {
            O[nt][0] *= a0; O[nt][1] *= a0;
            O[nt][2] *= a1; O[nt][3] *= a1;
        }

        // ---- O += P V ----
        #pragma unroll
        for (int ks = 0; ks < 4; ks++) {
            int j0 = 2 * ks, j1 = j0 + 1;
            unsigned ph0, ph1, ph2, ph3, pl0, pl1, pl2, pl3;
            splitpk(sa[j0][0], sa[j0][1], ph0, pl0);
            splitpk(sa[j0][2], sa[j0][3], ph1, pl1);
            splitpk(sa[j1][0], sa[j1][1], ph2, pl2);
            splitpk(sa[j1][2], sa[j1][3], ph3, pl3);
            unsigned vh4[4][4], vl4[4][4];
            #pragma unroll
            for (int p = 0; p < 4; p++) {
                unsigned off = vbb + ((vrow + ks * 16) * 72 + vc8 + p * 16) * 2;
                ldsm4t(vh4[p][0], vh4[p][1], vh4[p][2], vh4[p][3], off);
                ldsm4t(vl4[p][0], vl4[p][1], vl4[p][2], vl4[p][3], off + 9216);
            }
            #pragma unroll
            for (int nt = 0; nt < 8; nt++) {
                int p = nt >> 1, u = (nt & 1) * 2;
                mma16816(O[nt], ph0, ph1, ph2, ph3, vh4[p][u], vh4[p][u + 1]);
                mma16816(O[nt], ph0, ph1, ph2, ph3, vl4[p][u], vl4[p][u + 1]);
                mma16816(O[nt], pl0, pl1, pl2, pl3, vh4[p][u], vh4[p][u + 1]);
            }
        }
        __syncthreads();
    }

    // ---- Epilogue: normalize, split, write ctx hi/lo ----
    float i0 = 1.f / lr0, i1 = 1.f / lr1;
    size_t o1 = ((size_t)(b * S_ + r1)) * E_ + h * D_ + (lane & 3) * 2;
    size_t o2 = o1 + (size_t)8 * E_;
    #pragma unroll
    for (int nt = 0; nt < 8; nt++) {
        unsigned hw, lw;
        splitpk(O[nt][0] * i0, O[nt][1] * i0, hw, lw);
        *(unsigned*)(g_ch + o1 + nt * 8) = hw;
        *(unsigned*)(g_cl + o1 + nt * 8) = lw;
        splitpk(O[nt][2] * i1, O[nt][3] * i1, hw, lw);
        *(unsigned*)(g_ch + o2 + nt * 8) = hw;
        *(unsigned*)(g_cl + o2 + nt * 8) = lw;
    }
}

// ---------------------------------------------------------------------------
// Launch: split pass -> QKV GEMM -> flash -> output GEMM.
// ---------------------------------------------------------------------------
extern "C" void kernel_launch(void* const* d_in, const int* in_sizes, int n_in,
                              void* d_out, int out_size)
{
    const float* query = (const float*)d_in[0];
    const float* key   = (const float*)d_in[1];
    const float* value = (const float*)d_in[2];
    const float* qkvw  = (const float*)d_in[3];
    const float* qkvb  = (const float*)d_in[4];
    const float* projw = (const float*)d_in[5];
    const float* projb = (const float*)d_in[6];
    const float* mask  = (const float*)d_in[7];

    __nv_bfloat16 *xh, *xl, *wh, *wl, *ch, *cl;
    cudaGetSymbolAddress((void**)&xh, g_xh);
    cudaGetSymbolAddress((void**)&xl, g_xl);
    cudaGetSymbolAddress((void**)&wh, g_wh);
    cudaGetSymbolAddress((void**)&wl, g_wl);
    cudaGetSymbolAddress((void**)&ch, g_ch);
    cudaGetSymbolAddress((void**)&cl, g_cl);

    cudaFuncSetAttribute(gemm_bf16<1>, cudaFuncAttributeMaxDynamicSharedMemorySize, GEMM_SMEM);
    cudaFuncSetAttribute(gemm_bf16<0>, cudaFuncAttributeMaxDynamicSharedMemorySize, GEMM_SMEM);
    cudaFuncSetAttribute(flash_mma, cudaFuncAttributeMaxDynamicSharedMemorySize, FL_SMEM);

    // 1. split inputs + weights to bf16 hi/lo (4M float4)
    split_all<<<16384, 256>>>(query, key, value, qkvw, projw);

    // 2. fused QKV projection -> per-head split q/k/v
    gemm_bf16<1><<<dim3(24, 32), 256, GEMM_SMEM>>>(xh, xl, wh, wl, qkvb, nullptr);

    // 3. flash attention -> split ctx
    flash_mma<<<dim3(S_ / 128, B_ * H_), 256, FL_SMEM>>>(mask);

    // 4. output projection -> fp32 d_out
    gemm_bf16<0><<<dim3(8, 32), 256, GEMM_SMEM>>>(ch, cl,
                                                  wh + (size_t)3 * K_ * K_,
                                                  wl + (size_t)3 * K_ * K_,
                                                  projb, (float*)d_out);
}

// round 9
// speedup vs baseline: 2.8502x; 1.1469x over previous
#include <cuda_runtime.h>
#include <cuda_bf16.h>

#define B_ 2
#define S_ 2048
#define E_ 1024
#define H_ 16
#define D_ 64
#define M_ 4096
#define K_ 1024

// ---------------------------------------------------------------------------
// Scratch (__device__ globals). All bf16 hi/lo pairs.
// ---------------------------------------------------------------------------
__device__ __align__(256) __nv_bfloat16 g_xh[(size_t)3*M_*K_];  // split q/k/v inputs
__device__ __align__(256) __nv_bfloat16 g_xl[(size_t)3*M_*K_];
__device__ __align__(256) __nv_bfloat16 g_wh[(size_t)4*K_*K_];  // qkvw(3M) + projw(1M)
__device__ __align__(256) __nv_bfloat16 g_wl[(size_t)4*K_*K_];
__device__ __align__(256) __nv_bfloat16 g_sh[(size_t)3*B_*H_*S_*D_]; // split q/k/v heads
__device__ __align__(256) __nv_bfloat16 g_sl[(size_t)3*B_*H_*S_*D_];
__device__ __align__(256) __nv_bfloat16 g_ch[(size_t)M_*E_];    // split ctx
__device__ __align__(256) __nv_bfloat16 g_cl[(size_t)M_*E_];

// ---------------------------------------------------------------------------
// Helpers
// ---------------------------------------------------------------------------
__device__ __forceinline__ unsigned cvta_s(const void* p) {
    return (unsigned)__cvta_generic_to_shared(p);
}
__device__ __forceinline__ unsigned pk2(__nv_bfloat16 a, __nv_bfloat16 b) {
    return (unsigned)__bfloat16_as_ushort(a) | ((unsigned)__bfloat16_as_ushort(b) << 16);
}
__device__ __forceinline__ void splitpk(float x, float y, unsigned& h, unsigned& l) {
    __nv_bfloat16 hx = __float2bfloat16_rn(x);
    __nv_bfloat16 hy = __float2bfloat16_rn(y);
    float rx = x - __bfloat162float(hx);
    float ry = y - __bfloat162float(hy);
    h = pk2(hx, hy);
    l = pk2(__float2bfloat16_rn(rx), __float2bfloat16_rn(ry));
}
__device__ __forceinline__ void ldsm4(unsigned& r0, unsigned& r1, unsigned& r2, unsigned& r3,
                                      unsigned a) {
    asm volatile("ldmatrix.sync.aligned.m8n8.x4.shared.b16 {%0,%1,%2,%3}, [%4];"
                 : "=r"(r0), "=r"(r1), "=r"(r2), "=r"(r3) : "r"(a));
}
__device__ __forceinline__ void ldsm4t(unsigned& r0, unsigned& r1, unsigned& r2, unsigned& r3,
                                       unsigned a) {
    asm volatile("ldmatrix.sync.aligned.m8n8.x4.trans.shared.b16 {%0,%1,%2,%3}, [%4];"
                 : "=r"(r0), "=r"(r1), "=r"(r2), "=r"(r3) : "r"(a));
}
__device__ __forceinline__ void mma16816(float* c,
                                         unsigned a0, unsigned a1, unsigned a2, unsigned a3,
                                         unsigned b0, unsigned b1) {
    asm volatile(
        "mma.sync.aligned.m16n8k16.row.col.f32.bf16.bf16.f32 "
        "{%0,%1,%2,%3}, {%4,%5,%6,%7}, {%8,%9}, {%0,%1,%2,%3};"
        : "+f"(c[0]), "+f"(c[1]), "+f"(c[2]), "+f"(c[3])
        : "r"(a0), "r"(a1), "r"(a2), "r"(a3), "r"(b0), "r"(b1));
}
__device__ __forceinline__ void cpa16(unsigned dst, const void* src) {
    asm volatile("cp.async.cg.shared.global [%0], [%1], 16;" :: "r"(dst), "l"(src));
}
__device__ __forceinline__ void cpa_commit() {
    asm volatile("cp.async.commit_group;" ::: "memory");
}
template<int N>
__device__ __forceinline__ void cpa_wait() {
    asm volatile("cp.async.wait_group %0;" :: "n"(N) : "memory");
}

// ---------------------------------------------------------------------------
// Split pass: fp32 -> bf16 hi/lo for q/k/v inputs + qkv weight + proj weight.
// ---------------------------------------------------------------------------
__global__ void __launch_bounds__(256) split_all(
    const float* __restrict__ q, const float* __restrict__ k, const float* __restrict__ v,
    const float* __restrict__ qkvw, const float* __restrict__ projw)
{
    size_t i4 = (size_t)blockIdx.x * 256 + threadIdx.x;
    const size_t XQ = (size_t)M_ * K_ / 4;
    const size_t WQ = (size_t)3 * K_ * K_ / 4;
    const float* src; __nv_bfloat16 *dh, *dl; size_t o;
    if (i4 < 3 * XQ) {
        size_t sel = i4 / XQ; o = i4 - sel * XQ;
        src = (sel == 0) ? q : ((sel == 1) ? k : v);
        dh = g_xh + sel * (size_t)M_ * K_;
        dl = g_xl + sel * (size_t)M_ * K_;
    } else if (i4 < 3 * XQ + WQ) {
        o = i4 - 3 * XQ; src = qkvw; dh = g_wh; dl = g_wl;
    } else {
        o = i4 - 3 * XQ - WQ; src = projw;
        dh = g_wh + (size_t)3 * K_ * K_;
        dl = g_wl + (size_t)3 * K_ * K_;
    }
    float4 x = *((const float4*)src + o);
    unsigned h0, l0, h1, l1;
    splitpk(x.x, x.y, h0, l0);
    splitpk(x.z, x.w, h1, l1);
    *(uint2*)(dh + o * 4) = make_uint2(h0, h1);
    *(uint2*)(dl + o * 4) = make_uint2(l0, l1);
}

// ---------------------------------------------------------------------------
// bf16x3 GEMM on pre-split inputs. C[m][n] = sum_k A[m][k]*W[n][k] (+bias).
// CTA 128m x 64n, 8 warps (wm 0..3 x wn 0..1), warp tile 32x32 (acc 32 regs).
// K-chunk 64, cp.async double buffered: buffer 55296 B, total 110592 B
// -> 2 CTAs/SM; __launch_bounds__(256,2).
// Buffer arrays (byte offsets): Ah 0, Al 18432, Bh 36864, Bl 46080.
// QKV=1: A selected by n0>>10; epilogue -> per-head split q/k/v (q*1/8).
// ---------------------------------------------------------------------------
#define GEMM_BUF  55296
#define GEMM_SMEM (2 * GEMM_BUF)

template<int QKV>
__global__ void __launch_bounds__(256, 2) gemm_bf16(
    const __nv_bfloat16* __restrict__ Ah0, const __nv_bfloat16* __restrict__ Al0,
    const __nv_bfloat16* __restrict__ Wh, const __nv_bfloat16* __restrict__ Wl,
    const float* __restrict__ bias, float* __restrict__ out)
{
    extern __shared__ __align__(1024) __nv_bfloat16 smg[];
    const unsigned sb = cvta_s(smg);

    const int tid = threadIdx.x, lane = tid & 31, wid = tid >> 5;
    const int wm = wid & 3, wn = wid >> 2;
    const int m0 = blockIdx.y * 128, n0 = blockIdx.x * 64;

    const __nv_bfloat16* Ah = Ah0;
    const __nv_bfloat16* Al = Al0;
    int sel = 0;
    if (QKV) {
        sel = n0 >> 10;
        Ah += (size_t)sel * M_ * K_;
        Al += (size_t)sel * M_ * K_;
    }

    // cp.async mapping: A 1024 segs (4/thread), B 512 segs (2/thread)
    int ar[4], as_[4], asg[4];
    #pragma unroll
    for (int i = 0; i < 4; i++) {
        int idx = tid + 256 * i;
        ar[i] = idx >> 3;
        asg[i] = (idx & 7) * 8;
        as_[i] = (idx >> 3) * 144 + (idx & 7) * 16;
    }
    int br[2], bs_[2], bsg[2];
    #pragma unroll
    for (int i = 0; i < 2; i++) {
        int idx = tid + 256 * i;
        br[i] = idx >> 3;
        bsg[i] = (idx & 7) * 8;
        bs_[i] = (idx >> 3) * 144 + (idx & 7) * 16;
    }

    // preload chunk 0 -> buf 0
    #pragma unroll
    for (int i = 0; i < 4; i++) {
        unsigned d = sb + as_[i];
        size_t g = (size_t)(m0 + ar[i]) * K_ + asg[i];
        cpa16(d,         Ah + g);
        cpa16(d + 18432, Al + g);
    }
    #pragma unroll
    for (int i = 0; i < 2; i++) {
        unsigned d = sb + 36864 + bs_[i];
        size_t g = (size_t)(n0 + br[i]) * K_ + bsg[i];
        cpa16(d,        Wh + g);
        cpa16(d + 9216, Wl + g);
    }
    cpa_commit();

    float acc[2][4][4];
    #pragma unroll
    for (int mi = 0; mi < 2; mi++)
        #pragma unroll
        for (int nt = 0; nt < 4; nt++)
            #pragma unroll
            for (int q = 0; q < 4; q++) acc[mi][nt][q] = 0.f;

    const int arow = wm * 32 + (lane & 15);     // +mi*16
    const int ak8  = (lane >> 4) * 8;
    const int brow = wn * 32 + (lane >> 4) * 8 + (lane & 7);   // +p*16
    const int bk8  = ((lane >> 3) & 1) * 8;

    const int NC = K_ / 64;   // 16
    for (int c = 0; c < NC; c++) {
        if (c + 1 < NC) {
            const unsigned bb = sb + ((c + 1) & 1) * GEMM_BUF;
            const int ko = (c + 1) * 64;
            #pragma unroll
            for (int i = 0; i < 4; i++) {
                unsigned d = bb + as_[i];
                size_t g = (size_t)(m0 + ar[i]) * K_ + ko + asg[i];
                cpa16(d,         Ah + g);
                cpa16(d + 18432, Al + g);
            }
            #pragma unroll
            for (int i = 0; i < 2; i++) {
                unsigned d = bb + 36864 + bs_[i];
                size_t g = (size_t)(n0 + br[i]) * K_ + ko + bsg[i];
                cpa16(d,        Wh + g);
                cpa16(d + 9216, Wl + g);
            }
            cpa_commit();
            cpa_wait<1>();
        } else {
            cpa_wait<0>();
        }
        __syncthreads();

        const unsigned ab = sb + (c & 1) * GEMM_BUF;
        #pragma unroll
        for (int ks = 0; ks < 4; ks++) {
            unsigned ah[2][4], al[2][4];
            #pragma unroll
            for (int mi = 0; mi < 2; mi++) {
                unsigned off = ab + ((arow + mi * 16) * 72 + ks * 16 + ak8) * 2;
                ldsm4(ah[mi][0], ah[mi][1], ah[mi][2], ah[mi][3], off);
                ldsm4(al[mi][0], al[mi][1], al[mi][2], al[mi][3], off + 18432);
            }
            #pragma unroll
            for (int p = 0; p < 2; p++) {
                unsigned bh4[4], bl4[4];
                unsigned off = ab + 36864 + ((brow + p * 16) * 72 + ks * 16 + bk8) * 2;
                ldsm4(bh4[0], bh4[1], bh4[2], bh4[3], off);
                ldsm4(bl4[0], bl4[1], bl4[2], bl4[3], off + 9216);
                #pragma unroll
                for (int j = 0; j < 2; j++) {
                    const int nt = p * 2 + j, u = j * 2;
                    #pragma unroll
                    for (int mi = 0; mi < 2; mi++) {
                        mma16816(acc[mi][nt], ah[mi][0], ah[mi][1], ah[mi][2], ah[mi][3],
                                 bh4[u], bh4[u + 1]);
                        mma16816(acc[mi][nt], ah[mi][0], ah[mi][1], ah[mi][2], ah[mi][3],
                                 bl4[u], bl4[u + 1]);
                        mma16816(acc[mi][nt], al[mi][0], al[mi][1], al[mi][2], al[mi][3],
                                 bh4[u], bh4[u + 1]);
                    }
                }
            }
        }
        __syncthreads();
    }

    // Epilogue
    #pragma unroll
    for (int mi = 0; mi < 2; mi++) {
        const int row = m0 + wm * 32 + mi * 16 + (lane >> 2);
        #pragma unroll
        for (int nt = 0; nt < 4; nt++) {
            const int cg = n0 + wn * 32 + nt * 8 + (lane & 3) * 2;
            float2 bv = *(const float2*)(bias + cg);
            if (QKV) {
                const float scl = (sel == 0) ? 0.125f : 1.0f;
                const int nl = cg - (sel << 10);
                const int h = nl >> 6, d = nl & 63;
                const int bb2 = row >> 11, s = row & (S_ - 1);
                size_t base = ((size_t)((sel * 32 + bb2 * H_ + h) * S_ + s)) * D_ + d;
                unsigned hw, lw;
                splitpk((acc[mi][nt][0] + bv.x) * scl, (acc[mi][nt][1] + bv.y) * scl, hw, lw);
                *(unsigned*)(g_sh + base) = hw;
                *(unsigned*)(g_sl + base) = lw;
                splitpk((acc[mi][nt][2] + bv.x) * scl, (acc[mi][nt][3] + bv.y) * scl, hw, lw);
                *(unsigned*)(g_sh + base + 8 * D_) = hw;
                *(unsigned*)(g_sl + base + 8 * D_) = lw;
            } else {
                *(float2*)(out + (size_t)row * E_ + cg) =
                    make_float2(acc[mi][nt][0] + bv.x, acc[mi][nt][1] + bv.y);
                *(float2*)(out + (size_t)(row + 8) * E_ + cg) =
                    make_float2(acc[mi][nt][2] + bv.x, acc[mi][nt][3] + bv.y);
            }
        }
    }
}

// ---------------------------------------------------------------------------
// Flash attention, bf16x3 mma.sync. BR=64, BC=64, 128 threads (4 warps x 16
// rows). Q frags register-resident; K/V cp.async double-buffered. smem
// 73728 B -> 2 CTAs/SM. Epilogue writes ctx pre-split (g_ch/g_cl).
// Buffer arrays (byte offsets within 36864-B buffer): KH 0, KL 9216,
// VH 18432, VL 27648. Q staged in buf1 region before pipeline start.
// ---------------------------------------------------------------------------
#define FL_BUF  36864
#define FL_SMEM (2 * FL_BUF)

__global__ void __launch_bounds__(128, 2) flash_mma(const float* __restrict__ mask)
{
    extern __shared__ __align__(1024) __nv_bfloat16 smf[];
    const unsigned sb = cvta_s(smf);

    const int tid = threadIdx.x, lane = tid & 31, wid = tid >> 5;
    const int bh = blockIdx.y;                 // b*H + h
    const int row0 = blockIdx.x * 64;
    const int b = bh >> 4, h = bh & 15;

    const __nv_bfloat16* qhb = g_sh + ((size_t)bh * S_ + row0) * D_;
    const __nv_bfloat16* qlb = g_sl + ((size_t)bh * S_ + row0) * D_;
    const __nv_bfloat16* khb = g_sh + (size_t)(32 + bh) * S_ * D_;
    const __nv_bfloat16* klb = g_sl + (size_t)(32 + bh) * S_ * D_;
    const __nv_bfloat16* vhb = g_sh + (size_t)(64 + bh) * S_ * D_;
    const __nv_bfloat16* vlb = g_sl + (size_t)(64 + bh) * S_ * D_;

    // cp.async mapping: per 64x64 array 512 segs -> 4/thread
    int kr[4], kso[4], kgf[4];
    #pragma unroll
    for (int i = 0; i < 4; i++) {
        int idx = tid + 128 * i;
        kr[i] = idx >> 3;
        kso[i] = (idx >> 3) * 144 + (idx & 7) * 16;
        kgf[i] = (idx & 7) * 8;
    }

    // group 0: KV t=0 -> buf0
    #pragma unroll
    for (int i = 0; i < 4; i++) {
        unsigned d = sb + kso[i];
        size_t g = (size_t)kr[i] * D_ + kgf[i];
        cpa16(d,         khb + g);
        cpa16(d + 9216,  klb + g);
        cpa16(d + 18432, vhb + g);
        cpa16(d + 27648, vlb + g);
    }
    cpa_commit();
    // group 1: Q -> buf1 region (QH at +FL_BUF, QL at +FL_BUF+9216)
    #pragma unroll
    for (int i = 0; i < 4; i++) {
        unsigned d = sb + FL_BUF + kso[i];
        size_t g = (size_t)kr[i] * D_ + kgf[i];
        cpa16(d,        qhb + g);
        cpa16(d + 9216, qlb + g);
    }
    cpa_commit();
    cpa_wait<0>();
    __syncthreads();

    // Q frags -> registers
    unsigned qh[4][4], ql[4][4];
    {
        const int qrow = wid * 16 + (lane & 15);
        const int qk8 = (lane >> 4) * 8;
        #pragma unroll
        for (int ks = 0; ks < 4; ks++) {
            unsigned off = sb + FL_BUF + (qrow * 72 + ks * 16 + qk8) * 2;
            ldsm4(qh[ks][0], qh[ks][1], qh[ks][2], qh[ks][3], off);
            ldsm4(ql[ks][0], ql[ks][1], ql[ks][2], ql[ks][3], off + 9216);
        }
    }
    __syncthreads();   // all Q reads done before t=1 prefetch overwrites buf1

    float O[8][4];
    #pragma unroll
    for (int nt = 0; nt < 8; nt++)
        #pragma unroll
        for (int q = 0; q < 4; q++) O[nt][q] = 0.f;
    float mr0 = -1e30f, mr1 = -1e30f, lr0 = 0.f, lr1 = 0.f;

    const int krow = (lane >> 4) * 8 + (lane & 7);       // + p*16
    const int kk8  = ((lane >> 3) & 1) * 8;
    const int vrow = ((lane >> 3) & 1) * 8 + (lane & 7); // + ks*16
    const int vc8  = (lane >> 4) * 8;                    // + p*16

    const int r1 = row0 + wid * 16 + (lane >> 2);
    const float* mrow1 = mask + (size_t)r1 * S_;
    const float* mrow2 = mrow1 + 8 * S_;

    const int NT = S_ / 64;   // 32
    for (int t = 0; t < NT; t++) {
        if (t + 1 < NT) {
            const unsigned bb = sb + ((t + 1) & 1) * FL_BUF;
            #pragma unroll
            for (int i = 0; i < 4; i++) {
                unsigned d = bb + kso[i];
                size_t g = (size_t)((t + 1) * 64 + kr[i]) * D_ + kgf[i];
                cpa16(d,         khb + g);
                cpa16(d + 9216,  klb + g);
                cpa16(d + 18432, vhb + g);
                cpa16(d + 27648, vlb + g);
            }
            cpa_commit();
            cpa_wait<1>();
        } else {
            cpa_wait<0>();
        }
        __syncthreads();

        const unsigned kbb = sb + (t & 1) * FL_BUF;
        const unsigned vbb = kbb + 18432;

        // ---- S = Q K^T ----
        float sa[8][4];
        #pragma unroll
        for (int nt = 0; nt < 8; nt++)
            #pragma unroll
            for (int q = 0; q < 4; q++) sa[nt][q] = 0.f;

        #pragma unroll
        for (int ks = 0; ks < 4; ks++) {
            unsigned bh4[4][4], bl4[4][4];
            #pragma unroll
            for (int p = 0; p < 4; p++) {
                unsigned off = kbb + ((krow + p * 16) * 72 + ks * 16 + kk8) * 2;
                ldsm4(bh4[p][0], bh4[p][1], bh4[p][2], bh4[p][3], off);
                ldsm4(bl4[p][0], bl4[p][1], bl4[p][2], bl4[p][3], off + 9216);
            }
            #pragma unroll
            for (int nt = 0; nt < 8; nt++) {
                int p = nt >> 1, u = (nt & 1) * 2;
                mma16816(sa[nt], qh[ks][0], qh[ks][1], qh[ks][2], qh[ks][3],
                         bh4[p][u], bh4[p][u + 1]);
                mma16816(sa[nt], qh[ks][0], qh[ks][1], qh[ks][2], qh[ks][3],
                         bl4[p][u], bl4[p][u + 1]);
                mma16816(sa[nt], ql[ks][0], ql[ks][1], ql[ks][2], ql[ks][3],
                         bh4[p][u], bh4[p][u + 1]);
            }
        }

        // ---- mask + online softmax (warp-local) ----
        int cb = t * 64 + (lane & 3) * 2;
        float mx0 = -1e30f, mx1 = -1e30f;
        #pragma unroll
        for (int nt = 0; nt < 8; nt++) {
            float2 m1 = *(const float2*)(mrow1 + cb + nt * 8);
            float2 m2 = *(const float2*)(mrow2 + cb + nt * 8);
            sa[nt][0] += m1.x; sa[nt][1] += m1.y;
            sa[nt][2] += m2.x; sa[nt][3] += m2.y;
            mx0 = fmaxf(mx0, fmaxf(sa[nt][0], sa[nt][1]));
            mx1 = fmaxf(mx1, fmaxf(sa[nt][2], sa[nt][3]));
        }
        mx0 = fmaxf(mx0, __shfl_xor_sync(0xffffffffu, mx0, 1));
        mx0 = fmaxf(mx0, __shfl_xor_sync(0xffffffffu, mx0, 2));
        mx1 = fmaxf(mx1, __shfl_xor_sync(0xffffffffu, mx1, 1));
        mx1 = fmaxf(mx1, __shfl_xor_sync(0xffffffffu, mx1, 2));

        float mn0 = fmaxf(mr0, mx0), mn1 = fmaxf(mr1, mx1);
        float a0 = __expf(mr0 - mn0), a1 = __expf(mr1 - mn1);
        mr0 = mn0; mr1 = mn1;

        float s0 = 0.f, s1 = 0.f;
        #pragma unroll
        for (int nt = 0; nt < 8; nt++) {
            sa[nt][0] = __expf(sa[nt][0] - mn0); s0 += sa[nt][0];
            sa[nt][1] = __expf(sa[nt][1] - mn0); s0 += sa[nt][1];
            sa[nt][2] = __expf(sa[nt][2] - mn1); s1 += sa[nt][2];
            sa[nt][3] = __expf(sa[nt][3] - mn1); s1 += sa[nt][3];
        }
        s0 += __shfl_xor_sync(0xffffffffu, s0, 1);
        s0 += __shfl_xor_sync(0xffffffffu, s0, 2);
        s1 += __shfl_xor_sync(0xffffffffu, s1, 1);
        s1 += __shfl_xor_sync(0xffffffffu, s1, 2);
        lr0 = lr0 * a0 + s0;
        lr1 = lr1 * a1 + s1;
        #pragma unroll
        for (int nt = 0; nt < 8; nt++) {
            O[nt][0] *= a0; O[nt][1] *= a0;
            O[nt][2] *= a1; O[nt][3] *= a1;
        }

        // ---- O += P V ----
        #pragma unroll
        for (int ks = 0; ks < 4; ks++) {
            int j0 = 2 * ks, j1 = j0 + 1;
            unsigned ph0, ph1, ph2, ph3, pl0, pl1, pl2, pl3;
            splitpk(sa[j0][0], sa[j0][1], ph0, pl0);
            splitpk(sa[j0][2], sa[j0][3], ph1, pl1);
            splitpk(sa[j1][0], sa[j1][1], ph2, pl2);
            splitpk(sa[j1][2], sa[j1][3], ph3, pl3);
            unsigned vh4[4][4], vl4[4][4];
            #pragma unroll
            for (int p = 0; p < 4; p++) {
                unsigned off = vbb + ((vrow + ks * 16) * 72 + vc8 + p * 16) * 2;
                ldsm4t(vh4[p][0], vh4[p][1], vh4[p][2], vh4[p][3], off);
                ldsm4t(vl4[p][0], vl4[p][1], vl4[p][2], vl4[p][3], off + 9216);
            }
            #pragma unroll
            for (int nt = 0; nt < 8; nt++) {
                int p = nt >> 1, u = (nt & 1) * 2;
                mma16816(O[nt], ph0, ph1, ph2, ph3, vh4[p][u], vh4[p][u + 1]);
                mma16816(O[nt], ph0, ph1, ph2, ph3, vl4[p][u], vl4[p][u + 1]);
                mma16816(O[nt], pl0, pl1, pl2, pl3, vh4[p][u], vh4[p][u + 1]);
            }
        }
        __syncthreads();
    }

    // ---- Epilogue: normalize, split, write ctx hi/lo ----
    float i0 = 1.f / lr0, i1 = 1.f / lr1;
    size_t o1 = ((size_t)(b * S_ + r1)) * E_ + h * D_ + (lane & 3) * 2;
    size_t o2 = o1 + (size_t)8 * E_;
    #pragma unroll
    for (int nt = 0; nt < 8; nt++) {
        unsigned hw, lw;
        splitpk(O[nt][0] * i0, O[nt][1] * i0, hw, lw);
        *(unsigned*)(g_ch + o1 + nt * 8) = hw;
        *(unsigned*)(g_cl + o1 + nt * 8) = lw;
        splitpk(O[nt][2] * i1, O[nt][3] * i1, hw, lw);
        *(unsigned*)(g_ch + o2 + nt * 8) = hw;
        *(unsigned*)(g_cl + o2 + nt * 8) = lw;
    }
}

// ---------------------------------------------------------------------------
// Launch: split pass -> QKV GEMM -> flash -> output GEMM.
// ---------------------------------------------------------------------------
extern "C" void kernel_launch(void* const* d_in, const int* in_sizes, int n_in,
                              void* d_out, int out_size)
{
    const float* query = (const float*)d_in[0];
    const float* key   = (const float*)d_in[1];
    const float* value = (const float*)d_in[2];
    const float* qkvw  = (const float*)d_in[3];
    const float* qkvb  = (const float*)d_in[4];
    const float* projw = (const float*)d_in[5];
    const float* projb = (const float*)d_in[6];
    const float* mask  = (const float*)d_in[7];

    __nv_bfloat16 *xh, *xl, *wh, *wl, *ch, *cl;
    cudaGetSymbolAddress((void**)&xh, g_xh);
    cudaGetSymbolAddress((void**)&xl, g_xl);
    cudaGetSymbolAddress((void**)&wh, g_wh);
    cudaGetSymbolAddress((void**)&wl, g_wl);
    cudaGetSymbolAddress((void**)&ch, g_ch);
    cudaGetSymbolAddress((void**)&cl, g_cl);

    cudaFuncSetAttribute(gemm_bf16<1>, cudaFuncAttributeMaxDynamicSharedMemorySize, GEMM_SMEM);
    cudaFuncSetAttribute(gemm_bf16<0>, cudaFuncAttributeMaxDynamicSharedMemorySize, GEMM_SMEM);
    cudaFuncSetAttribute(flash_mma, cudaFuncAttributeMaxDynamicSharedMemorySize, FL_SMEM);

    // 1. split inputs + weights to bf16 hi/lo
    split_all<<<16384, 256>>>(query, key, value, qkvw, projw);

    // 2. fused QKV projection -> per-head split q/k/v   (48 x 32 = 1536 CTAs)
    gemm_bf16<1><<<dim3(48, 32), 256, GEMM_SMEM>>>(xh, xl, wh, wl, qkvb, nullptr);

    // 3. flash attention -> split ctx                   (32 x 32 = 1024 CTAs)
    flash_mma<<<dim3(S_ / 64, B_ * H_), 128, FL_SMEM>>>(mask);

    // 4. output projection -> fp32 d_out                (16 x 32 = 512 CTAs)
    gemm_bf16<0><<<dim3(16, 32), 256, GEMM_SMEM>>>(ch, cl,
                                                   wh + (size_t)3 * K_ * K_,
                                                   wl + (size_t)3 * K_ * K_,
                                                   projb, (float*)d_out);
}

// round 10
// speedup vs baseline: 2.9924x; 1.0499x over previous
#include <cuda_runtime.h>
#include <cuda_bf16.h>

#define B_ 2
#define S_ 2048
#define E_ 1024
#define H_ 16
#define D_ 64
#define M_ 4096
#define K_ 1024

// ---------------------------------------------------------------------------
// Scratch (__device__ globals). All bf16 hi/lo pairs.
// ---------------------------------------------------------------------------
__device__ __align__(256) __nv_bfloat16 g_xh[(size_t)3*M_*K_];  // split q/k/v inputs
__device__ __align__(256) __nv_bfloat16 g_xl[(size_t)3*M_*K_];
__device__ __align__(256) __nv_bfloat16 g_wh[(size_t)4*K_*K_];  // qkvw(3M) + projw(1M)
__device__ __align__(256) __nv_bfloat16 g_wl[(size_t)4*K_*K_];
__device__ __align__(256) __nv_bfloat16 g_sh[(size_t)3*B_*H_*S_*D_]; // split q/k/v heads
__device__ __align__(256) __nv_bfloat16 g_sl[(size_t)3*B_*H_*S_*D_];
__device__ __align__(256) __nv_bfloat16 g_ch[(size_t)M_*E_];    // split ctx
__device__ __align__(256) __nv_bfloat16 g_cl[(size_t)M_*E_];

// ---------------------------------------------------------------------------
// Helpers
// ---------------------------------------------------------------------------
__device__ __forceinline__ unsigned cvta_s(const void* p) {
    return (unsigned)__cvta_generic_to_shared(p);
}
__device__ __forceinline__ unsigned pk2(__nv_bfloat16 a, __nv_bfloat16 b) {
    return (unsigned)__bfloat16_as_ushort(a) | ((unsigned)__bfloat16_as_ushort(b) << 16);
}
__device__ __forceinline__ void splitpk(float x, float y, unsigned& h, unsigned& l) {
    __nv_bfloat16 hx = __float2bfloat16_rn(x);
    __nv_bfloat16 hy = __float2bfloat16_rn(y);
    float rx = x - __bfloat162float(hx);
    float ry = y - __bfloat162float(hy);
    h = pk2(hx, hy);
    l = pk2(__float2bfloat16_rn(rx), __float2bfloat16_rn(ry));
}
__device__ __forceinline__ void ldsm4(unsigned& r0, unsigned& r1, unsigned& r2, unsigned& r3,
                                      unsigned a) {
    asm volatile("ldmatrix.sync.aligned.m8n8.x4.shared.b16 {%0,%1,%2,%3}, [%4];"
                 : "=r"(r0), "=r"(r1), "=r"(r2), "=r"(r3) : "r"(a));
}
__device__ __forceinline__ void ldsm4t(unsigned& r0, unsigned& r1, unsigned& r2, unsigned& r3,
                                       unsigned a) {
    asm volatile("ldmatrix.sync.aligned.m8n8.x4.trans.shared.b16 {%0,%1,%2,%3}, [%4];"
                 : "=r"(r0), "=r"(r1), "=r"(r2), "=r"(r3) : "r"(a));
}
__device__ __forceinline__ void mma16816(float* c,
                                         unsigned a0, unsigned a1, unsigned a2, unsigned a3,
                                         unsigned b0, unsigned b1) {
    asm volatile(
        "mma.sync.aligned.m16n8k16.row.col.f32.bf16.bf16.f32 "
        "{%0,%1,%2,%3}, {%4,%5,%6,%7}, {%8,%9}, {%0,%1,%2,%3};"
        : "+f"(c[0]), "+f"(c[1]), "+f"(c[2]), "+f"(c[3])
        : "r"(a0), "r"(a1), "r"(a2), "r"(a3), "r"(b0), "r"(b1));
}
__device__ __forceinline__ void cpa16(unsigned dst, const void* src) {
    asm volatile("cp.async.cg.shared.global [%0], [%1], 16;" :: "r"(dst), "l"(src));
}
__device__ __forceinline__ void cpa_commit() {
    asm volatile("cp.async.commit_group;" ::: "memory");
}
template<int N>
__device__ __forceinline__ void cpa_wait() {
    asm volatile("cp.async.wait_group %0;" :: "n"(N) : "memory");
}

// ---------------------------------------------------------------------------
// Split pass: fp32 -> bf16 hi/lo for q/k/v inputs + qkv weight + proj weight.
// ---------------------------------------------------------------------------
__global__ void __launch_bounds__(256) split_all(
    const float* __restrict__ q, const float* __restrict__ k, const float* __restrict__ v,
    const float* __restrict__ qkvw, const float* __restrict__ projw)
{
    size_t i4 = (size_t)blockIdx.x * 256 + threadIdx.x;
    const size_t XQ = (size_t)M_ * K_ / 4;
    const size_t WQ = (size_t)3 * K_ * K_ / 4;
    const float* src; __nv_bfloat16 *dh, *dl; size_t o;
    if (i4 < 3 * XQ) {
        size_t sel = i4 / XQ; o = i4 - sel * XQ;
        src = (sel == 0) ? q : ((sel == 1) ? k : v);
        dh = g_xh + sel * (size_t)M_ * K_;
        dl = g_xl + sel * (size_t)M_ * K_;
    } else if (i4 < 3 * XQ + WQ) {
        o = i4 - 3 * XQ; src = qkvw; dh = g_wh; dl = g_wl;
    } else {
        o = i4 - 3 * XQ - WQ; src = projw;
        dh = g_wh + (size_t)3 * K_ * K_;
        dl = g_wl + (size_t)3 * K_ * K_;
    }
    float4 x = *((const float4*)src + o);
    unsigned h0, l0, h1, l1;
    splitpk(x.x, x.y, h0, l0);
    splitpk(x.z, x.w, h1, l1);
    *(uint2*)(dh + o * 4) = make_uint2(h0, h1);
    *(uint2*)(dl + o * 4) = make_uint2(l0, l1);
}

// ---------------------------------------------------------------------------
// bf16x3 GEMM on pre-split inputs (unchanged from R9).
// CTA 128m x 64n, 8 warps, warp tile 32x32. K-chunk 64, cp.async double
// buffered: 110592 B total -> 2 CTAs/SM.
// ---------------------------------------------------------------------------
#define GEMM_BUF  55296
#define GEMM_SMEM (2 * GEMM_BUF)

template<int QKV>
__global__ void __launch_bounds__(256, 2) gemm_bf16(
    const __nv_bfloat16* __restrict__ Ah0, const __nv_bfloat16* __restrict__ Al0,
    const __nv_bfloat16* __restrict__ Wh, const __nv_bfloat16* __restrict__ Wl,
    const float* __restrict__ bias, float* __restrict__ out)
{
    extern __shared__ __align__(1024) __nv_bfloat16 smg[];
    const unsigned sb = cvta_s(smg);

    const int tid = threadIdx.x, lane = tid & 31, wid = tid >> 5;
    const int wm = wid & 3, wn = wid >> 2;
    const int m0 = blockIdx.y * 128, n0 = blockIdx.x * 64;

    const __nv_bfloat16* Ah = Ah0;
    const __nv_bfloat16* Al = Al0;
    int sel = 0;
    if (QKV) {
        sel = n0 >> 10;
        Ah += (size_t)sel * M_ * K_;
        Al += (size_t)sel * M_ * K_;
    }

    int ar[4], as_[4], asg[4];
    #pragma unroll
    for (int i = 0; i < 4; i++) {
        int idx = tid + 256 * i;
        ar[i] = idx >> 3;
        asg[i] = (idx & 7) * 8;
        as_[i] = (idx >> 3) * 144 + (idx & 7) * 16;
    }
    int br[2], bs_[2], bsg[2];
    #pragma unroll
    for (int i = 0; i < 2; i++) {
        int idx = tid + 256 * i;
        br[i] = idx >> 3;
        bsg[i] = (idx & 7) * 8;
        bs_[i] = (idx >> 3) * 144 + (idx & 7) * 16;
    }

    #pragma unroll
    for (int i = 0; i < 4; i++) {
        unsigned d = sb + as_[i];
        size_t g = (size_t)(m0 + ar[i]) * K_ + asg[i];
        cpa16(d,         Ah + g);
        cpa16(d + 18432, Al + g);
    }
    #pragma unroll
    for (int i = 0; i < 2; i++) {
        unsigned d = sb + 36864 + bs_[i];
        size_t g = (size_t)(n0 + br[i]) * K_ + bsg[i];
        cpa16(d,        Wh + g);
        cpa16(d + 9216, Wl + g);
    }
    cpa_commit();

    float acc[2][4][4];
    #pragma unroll
    for (int mi = 0; mi < 2; mi++)
        #pragma unroll
        for (int nt = 0; nt < 4; nt++)
            #pragma unroll
            for (int q = 0; q < 4; q++) acc[mi][nt][q] = 0.f;

    const int arow = wm * 32 + (lane & 15);
    const int ak8  = (lane >> 4) * 8;
    const int brow = wn * 32 + (lane >> 4) * 8 + (lane & 7);
    const int bk8  = ((lane >> 3) & 1) * 8;

    const int NC = K_ / 64;
    for (int c = 0; c < NC; c++) {
        if (c + 1 < NC) {
            const unsigned bb = sb + ((c + 1) & 1) * GEMM_BUF;
            const int ko = (c + 1) * 64;
            #pragma unroll
            for (int i = 0; i < 4; i++) {
                unsigned d = bb + as_[i];
                size_t g = (size_t)(m0 + ar[i]) * K_ + ko + asg[i];
                cpa16(d,         Ah + g);
                cpa16(d + 18432, Al + g);
            }
            #pragma unroll
            for (int i = 0; i < 2; i++) {
                unsigned d = bb + 36864 + bs_[i];
                size_t g = (size_t)(n0 + br[i]) * K_ + ko + bsg[i];
                cpa16(d,        Wh + g);
                cpa16(d + 9216, Wl + g);
            }
            cpa_commit();
            cpa_wait<1>();
        } else {
            cpa_wait<0>();
        }
        __syncthreads();

        const unsigned ab = sb + (c & 1) * GEMM_BUF;
        #pragma unroll
        for (int ks = 0; ks < 4; ks++) {
            unsigned ah[2][4], al[2][4];
            #pragma unroll
            for (int mi = 0; mi < 2; mi++) {
                unsigned off = ab + ((arow + mi * 16) * 72 + ks * 16 + ak8) * 2;
                ldsm4(ah[mi][0], ah[mi][1], ah[mi][2], ah[mi][3], off);
                ldsm4(al[mi][0], al[mi][1], al[mi][2], al[mi][3], off + 18432);
            }
            #pragma unroll
            for (int p = 0; p < 2; p++) {
                unsigned bh4[4], bl4[4];
                unsigned off = ab + 36864 + ((brow + p * 16) * 72 + ks * 16 + bk8) * 2;
                ldsm4(bh4[0], bh4[1], bh4[2], bh4[3], off);
                ldsm4(bl4[0], bl4[1], bl4[2], bl4[3], off + 9216);
                #pragma unroll
                for (int j = 0; j < 2; j++) {
                    const int nt = p * 2 + j, u = j * 2;
                    #pragma unroll
                    for (int mi = 0; mi < 2; mi++) {
                        mma16816(acc[mi][nt], ah[mi][0], ah[mi][1], ah[mi][2], ah[mi][3],
                                 bh4[u], bh4[u + 1]);
                        mma16816(acc[mi][nt], ah[mi][0], ah[mi][1], ah[mi][2], ah[mi][3],
                                 bl4[u], bl4[u + 1]);
                        mma16816(acc[mi][nt], al[mi][0], al[mi][1], al[mi][2], al[mi][3],
                                 bh4[u], bh4[u + 1]);
                    }
                }
            }
        }
        __syncthreads();
    }

    #pragma unroll
    for (int mi = 0; mi < 2; mi++) {
        const int row = m0 + wm * 32 + mi * 16 + (lane >> 2);
        #pragma unroll
        for (int nt = 0; nt < 4; nt++) {
            const int cg = n0 + wn * 32 + nt * 8 + (lane & 3) * 2;
            float2 bv = *(const float2*)(bias + cg);
            if (QKV) {
                const float scl = (sel == 0) ? 0.125f : 1.0f;
                const int nl = cg - (sel << 10);
                const int h = nl >> 6, d = nl & 63;
                const int bb2 = row >> 11, s = row & (S_ - 1);
                size_t base = ((size_t)((sel * 32 + bb2 * H_ + h) * S_ + s)) * D_ + d;
                unsigned hw, lw;
                splitpk((acc[mi][nt][0] + bv.x) * scl, (acc[mi][nt][1] + bv.y) * scl, hw, lw);
                *(unsigned*)(g_sh + base) = hw;
                *(unsigned*)(g_sl + base) = lw;
                splitpk((acc[mi][nt][2] + bv.x) * scl, (acc[mi][nt][3] + bv.y) * scl, hw, lw);
                *(unsigned*)(g_sh + base + 8 * D_) = hw;
                *(unsigned*)(g_sl + base + 8 * D_) = lw;
            } else {
                *(float2*)(out + (size_t)row * E_ + cg) =
                    make_float2(acc[mi][nt][0] + bv.x, acc[mi][nt][1] + bv.y);
                *(float2*)(out + (size_t)(row + 8) * E_ + cg) =
                    make_float2(acc[mi][nt][2] + bv.x, acc[mi][nt][3] + bv.y);
            }
        }
    }
}

// ---------------------------------------------------------------------------
// Flash attention, bf16x3 mma.sync. BR=64, BC=64, 128 threads.
// R10 changes: 3 CTAs/SM (launch_bounds(128,3); 3 x 73728 = 221 KB smem),
// mask loads hoisted to iteration start (L2 latency hidden under QK MMAs).
// ---------------------------------------------------------------------------
#define FL_BUF  36864
#define FL_SMEM (2 * FL_BUF)

__global__ void __launch_bounds__(128, 3) flash_mma(const float* __restrict__ mask)
{
    extern __shared__ __align__(1024) __nv_bfloat16 smf[];
    const unsigned sb = cvta_s(smf);

    const int tid = threadIdx.x, lane = tid & 31, wid = tid >> 5;
    const int bh = blockIdx.y;                 // b*H + h
    const int row0 = blockIdx.x * 64;
    const int b = bh >> 4, h = bh & 15;

    const __nv_bfloat16* qhb = g_sh + ((size_t)bh * S_ + row0) * D_;
    const __nv_bfloat16* qlb = g_sl + ((size_t)bh * S_ + row0) * D_;
    const __nv_bfloat16* khb = g_sh + (size_t)(32 + bh) * S_ * D_;
    const __nv_bfloat16* klb = g_sl + (size_t)(32 + bh) * S_ * D_;
    const __nv_bfloat16* vhb = g_sh + (size_t)(64 + bh) * S_ * D_;
    const __nv_bfloat16* vlb = g_sl + (size_t)(64 + bh) * S_ * D_;

    // cp.async mapping: per 64x64 array 512 segs -> 4/thread
    int kr[4], kso[4], kgf[4];
    #pragma unroll
    for (int i = 0; i < 4; i++) {
        int idx = tid + 128 * i;
        kr[i] = idx >> 3;
        kso[i] = (idx >> 3) * 144 + (idx & 7) * 16;
        kgf[i] = (idx & 7) * 8;
    }

    // group 0: KV t=0 -> buf0
    #pragma unroll
    for (int i = 0; i < 4; i++) {
        unsigned d = sb + kso[i];
        size_t g = (size_t)kr[i] * D_ + kgf[i];
        cpa16(d,         khb + g);
        cpa16(d + 9216,  klb + g);
        cpa16(d + 18432, vhb + g);
        cpa16(d + 27648, vlb + g);
    }
    cpa_commit();
    // group 1: Q -> buf1 region
    #pragma unroll
    for (int i = 0; i < 4; i++) {
        unsigned d = sb + FL_BUF + kso[i];
        size_t g = (size_t)kr[i] * D_ + kgf[i];
        cpa16(d,        qhb + g);
        cpa16(d + 9216, qlb + g);
    }
    cpa_commit();
    cpa_wait<0>();
    __syncthreads();

    // Q frags -> registers
    unsigned qh[4][4], ql[4][4];
    {
        const int qrow = wid * 16 + (lane & 15);
        const int qk8 = (lane >> 4) * 8;
        #pragma unroll
        for (int ks = 0; ks < 4; ks++) {
            unsigned off = sb + FL_BUF + (qrow * 72 + ks * 16 + qk8) * 2;
            ldsm4(qh[ks][0], qh[ks][1], qh[ks][2], qh[ks][3], off);
            ldsm4(ql[ks][0], ql[ks][1], ql[ks][2], ql[ks][3], off + 9216);
        }
    }
    __syncthreads();   // all Q reads done before t=1 prefetch overwrites buf1

    float O[8][4];
    #pragma unroll
    for (int nt = 0; nt < 8; nt++)
        #pragma unroll
        for (int q = 0; q < 4; q++) O[nt][q] = 0.f;
    float mr0 = -1e30f, mr1 = -1e30f, lr0 = 0.f, lr1 = 0.f;

    const int krow = (lane >> 4) * 8 + (lane & 7);       // + p*16
    const int kk8  = ((lane >> 3) & 1) * 8;
    const int vrow = ((lane >> 3) & 1) * 8 + (lane & 7); // + ks*16
    const int vc8  = (lane >> 4) * 8;                    // + p*16

    const int r1 = row0 + wid * 16 + (lane >> 2);
    const float* mrow1 = mask + (size_t)r1 * S_;
    const float* mrow2 = mrow1 + 8 * S_;

    const int NT = S_ / 64;   // 32
    for (int t = 0; t < NT; t++) {
        // ---- hoisted mask loads: issue LDGs first, consume after QK MMAs ----
        const int cb = t * 64 + (lane & 3) * 2;
        float2 mk1[8], mk2[8];
        #pragma unroll
        for (int nt = 0; nt < 8; nt++) {
            mk1[nt] = *(const float2*)(mrow1 + cb + nt * 8);
            mk2[nt] = *(const float2*)(mrow2 + cb + nt * 8);
        }

        if (t + 1 < NT) {
            const unsigned bb = sb + ((t + 1) & 1) * FL_BUF;
            #pragma unroll
            for (int i = 0; i < 4; i++) {
                unsigned d = bb + kso[i];
                size_t g = (size_t)((t + 1) * 64 + kr[i]) * D_ + kgf[i];
                cpa16(d,         khb + g);
                cpa16(d + 9216,  klb + g);
                cpa16(d + 18432, vhb + g);
                cpa16(d + 27648, vlb + g);
            }
            cpa_commit();
            cpa_wait<1>();
        } else {
            cpa_wait<0>();
        }
        __syncthreads();

        const unsigned kbb = sb + (t & 1) * FL_BUF;
        const unsigned vbb = kbb + 18432;

        // ---- S = Q K^T ----
        float sa[8][4];
        #pragma unroll
        for (int nt = 0; nt < 8; nt++)
            #pragma unroll
            for (int q = 0; q < 4; q++) sa[nt][q] = 0.f;

        #pragma unroll
        for (int ks = 0; ks < 4; ks++) {
            unsigned bh4[4][4], bl4[4][4];
            #pragma unroll
            for (int p = 0; p < 4; p++) {
                unsigned off = kbb + ((krow + p * 16) * 72 + ks * 16 + kk8) * 2;
                ldsm4(bh4[p][0], bh4[p][1], bh4[p][2], bh4[p][3], off);
                ldsm4(bl4[p][0], bl4[p][1], bl4[p][2], bl4[p][3], off + 9216);
            }
            #pragma unroll
            for (int nt = 0; nt < 8; nt++) {
                int p = nt >> 1, u = (nt & 1) * 2;
                mma16816(sa[nt], qh[ks][0], qh[ks][1], qh[ks][2], qh[ks][3],
                         bh4[p][u], bh4[p][u + 1]);
                mma16816(sa[nt], qh[ks][0], qh[ks][1], qh[ks][2], qh[ks][3],
                         bl4[p][u], bl4[p][u + 1]);
                mma16816(sa[nt], ql[ks][0], ql[ks][1], ql[ks][2], ql[ks][3],
                         bh4[p][u], bh4[p][u + 1]);
            }
        }

        // ---- mask + online softmax (warp-local) ----
        float mx0 = -1e30f, mx1 = -1e30f;
        #pragma unroll
        for (int nt = 0; nt < 8; nt++) {
            sa[nt][0] += mk1[nt].x; sa[nt][1] += mk1[nt].y;
            sa[nt][2] += mk2[nt].x; sa[nt][3] += mk2[nt].y;
            mx0 = fmaxf(mx0, fmaxf(sa[nt][0], sa[nt][1]));
            mx1 = fmaxf(mx1, fmaxf(sa[nt][2], sa[nt][3]));
        }
        mx0 = fmaxf(mx0, __shfl_xor_sync(0xffffffffu, mx0, 1));
        mx0 = fmaxf(mx0, __shfl_xor_sync(0xffffffffu, mx0, 2));
        mx1 = fmaxf(mx1, __shfl_xor_sync(0xffffffffu, mx1, 1));
        mx1 = fmaxf(mx1, __shfl_xor_sync(0xffffffffu, mx1, 2));

        float mn0 = fmaxf(mr0, mx0), mn1 = fmaxf(mr1, mx1);
        float a0 = __expf(mr0 - mn0), a1 = __expf(mr1 - mn1);
        mr0 = mn0; mr1 = mn1;

        float s0 = 0.f, s1 = 0.f;
        #pragma unroll
        for (int nt = 0; nt < 8; nt++) {
            sa[nt][0] = __expf(sa[nt][0] - mn0); s0 += sa[nt][0];
            sa[nt][1] = __expf(sa[nt][1] - mn0); s0 += sa[nt][1];
            sa[nt][2] = __expf(sa[nt][2] - mn1); s1 += sa[nt][2];
            sa[nt][3] = __expf(sa[nt][3] - mn1); s1 += sa[nt][3];
        }
        s0 += __shfl_xor_sync(0xffffffffu, s0, 1);
        s0 += __shfl_xor_sync(0xffffffffu, s0, 2);
        s1 += __shfl_xor_sync(0xffffffffu, s1, 1);
        s1 += __shfl_xor_sync(0xffffffffu, s1, 2);
        lr0 = lr0 * a0 + s0;
        lr1 = lr1 * a1 + s1;
        #pragma unroll
        for (int nt = 0; nt < 8; nt++) {
            O[nt][0] *= a0; O[nt][1] *= a0;
            O[nt][2] *= a1; O[nt][3] *= a1;
        }

        // ---- O += P V ----
        #pragma unroll
        for (int ks = 0; ks < 4; ks++) {
            int j0 = 2 * ks, j1 = j0 + 1;
            unsigned ph0, ph1, ph2, ph3, pl0, pl1, pl2, pl3;
            splitpk(sa[j0][0], sa[j0][1], ph0, pl0);
            splitpk(sa[j0][2], sa[j0][3], ph1, pl1);
            splitpk(sa[j1][0], sa[j1][1], ph2, pl2);
            splitpk(sa[j1][2], sa[j1][3], ph3, pl3);
            unsigned vh4[4][4], vl4[4][4];
            #pragma unroll
            for (int p = 0; p < 4; p++) {
                unsigned off = vbb + ((vrow + ks * 16) * 72 + vc8 + p * 16) * 2;
                ldsm4t(vh4[p][0], vh4[p][1], vh4[p][2], vh4[p][3], off);
                ldsm4t(vl4[p][0], vl4[p][1], vl4[p][2], vl4[p][3], off + 9216);
            }
            #pragma unroll
            for (int nt = 0; nt < 8; nt++) {
                int p = nt >> 1, u = (nt & 1) * 2;
                mma16816(O[nt], ph0, ph1, ph2, ph3, vh4[p][u], vh4[p][u + 1]);
                mma16816(O[nt], ph0, ph1, ph2, ph3, vl4[p][u], vl4[p][u + 1]);
                mma16816(O[nt], pl0, pl1, pl2, pl3, vh4[p][u], vh4[p][u + 1]);
            }
        }
        __syncthreads();
    }

    // ---- Epilogue: normalize, split, write ctx hi/lo ----
    float i0 = 1.f / lr0, i1 = 1.f / lr1;
    size_t o1 = ((size_t)(b * S_ + r1)) * E_ + h * D_ + (lane & 3) * 2;
    size_t o2 = o1 + (size_t)8 * E_;
    #pragma unroll
    for (int nt = 0; nt < 8; nt++) {
        unsigned hw, lw;
        splitpk(O[nt][0] * i0, O[nt][1] * i0, hw, lw);
        *(unsigned*)(g_ch + o1 + nt * 8) = hw;
        *(unsigned*)(g_cl + o1 + nt * 8) = lw;
        splitpk(O[nt][2] * i1, O[nt][3] * i1, hw, lw);
        *(unsigned*)(g_ch + o2 + nt * 8) = hw;
        *(unsigned*)(g_cl + o2 + nt * 8) = lw;
    }
}

// ---------------------------------------------------------------------------
// Launch: split pass -> QKV GEMM -> flash -> output GEMM.
// ---------------------------------------------------------------------------
extern "C" void kernel_launch(void* const* d_in, const int* in_sizes, int n_in,
                              void* d_out, int out_size)
{
    const float* query = (const float*)d_in[0];
    const float* key   = (const float*)d_in[1];
    const float* value = (const float*)d_in[2];
    const float* qkvw  = (const float*)d_in[3];
    const float* qkvb  = (const float*)d_in[4];
    const float* projw = (const float*)d_in[5];
    const float* projb = (const float*)d_in[6];
    const float* mask  = (const float*)d_in[7];

    __nv_bfloat16 *xh, *xl, *wh, *wl, *ch, *cl;
    cudaGetSymbolAddress((void**)&xh, g_xh);
    cudaGetSymbolAddress((void**)&xl, g_xl);
    cudaGetSymbolAddress((void**)&wh, g_wh);
    cudaGetSymbolAddress((void**)&wl, g_wl);
    cudaGetSymbolAddress((void**)&ch, g_ch);
    cudaGetSymbolAddress((void**)&cl, g_cl);

    cudaFuncSetAttribute(gemm_bf16<1>, cudaFuncAttributeMaxDynamicSharedMemorySize, GEMM_SMEM);
    cudaFuncSetAttribute(gemm_bf16<0>, cudaFuncAttributeMaxDynamicSharedMemorySize, GEMM_SMEM);
    cudaFuncSetAttribute(flash_mma, cudaFuncAttributeMaxDynamicSharedMemorySize, FL_SMEM);

    // 1. split inputs + weights to bf16 hi/lo
    split_all<<<16384, 256>>>(query, key, value, qkvw, projw);

    // 2. fused QKV projection -> per-head split q/k/v   (48 x 32 = 1536 CTAs)
    gemm_bf16<1><<<dim3(48, 32), 256, GEMM_SMEM>>>(xh, xl, wh, wl, qkvb, nullptr);

    // 3. flash attention -> split ctx                   (32 x 32 = 1024 CTAs)
    flash_mma<<<dim3(S_ / 64, B_ * H_), 128, FL_SMEM>>>(mask);

    // 4. output projection -> fp32 d_out                (16 x 32 = 512 CTAs)
    gemm_bf16<0><<<dim3(16, 32), 256, GEMM_SMEM>>>(ch, cl,
                                                   wh + (size_t)3 * K_ * K_,
                                                   wl + (size_t)3 * K_ * K_,
                                                   projb, (float*)d_out);
}